// round 3
// baseline (speedup 1.0000x reference)
#include <cuda_runtime.h>
#include <cuda_bf16.h>
#include <mma.h>
#include <math.h>

using namespace nvcuda;

#define NB 16
#define NN 8192
#define NC 256
#define NH 4
#define NK 64
#define NCHUNK 8

// Scratch (__device__ globals; no allocations allowed)
static __device__ float g_part[NCHUNK * NB * NC * NK];          // 8 MB partials
static __device__ float g_gvp[NB * NH * 64 * 64];               // fp32 global_vp [k][m]
static __device__ __nv_bfloat16 g_ef2h[NN * NK], g_ef2l[NN * NK];        // [n][k]
static __device__ __nv_bfloat16 g_skph[NB * NC * NK], g_skpl[NB * NC * NK]; // [b][h][k][d]
static __device__ __nv_bfloat16 g_vph[NB * NH * 64 * 64], g_vpl[NB * NH * 64 * 64]; // [b][h][m][k]

__device__ __forceinline__ void split2(float v, __nv_bfloat16& hi, __nv_bfloat16& lo) {
    hi = __float2bfloat16_rn(v);
    lo = __float2bfloat16_rn(v - __bfloat162float(hi));
}

// mma.sync m16n8k16 row.col bf16 -> f32, D += A*B
__device__ __forceinline__ void mma16816(float* c, const unsigned* a, const unsigned* b) {
    asm volatile(
        "mma.sync.aligned.m16n8k16.row.col.f32.bf16.bf16.f32 "
        "{%0,%1,%2,%3}, {%4,%5,%6,%7}, {%8,%9}, {%0,%1,%2,%3};"
        : "+f"(c[0]), "+f"(c[1]), "+f"(c[2]), "+f"(c[3])
        : "r"(a[0]), "r"(a[1]), "r"(a[2]), "r"(a[3]), "r"(b[0]), "r"(b[1]));
}

__device__ __forceinline__ unsigned pack_bf16(__nv_bfloat16 lo, __nv_bfloat16 hi) {
    __nv_bfloat162 p = __halves2bfloat162(lo, hi);   // .x = low half
    return *(unsigned*)&p;
}

// ---------------------------------------------------------------------------
__global__ void k_prep_ef2(const float* __restrict__ ef2) {
    int i = blockIdx.x * 256 + threadIdx.x;
    split2(ef2[i], g_ef2h[i], g_ef2l[i]);
}

// global_vp (fp32, tiny): g_gvp[bh][d1][m] = sum_n1 gf[b,n1,h*64+d1]*EF1[n1,m]
__global__ void k_gvp(const float* __restrict__ gf, const float* __restrict__ ef1) {
    int bh = blockIdx.x, b = bh >> 2, h = bh & 3;
    __shared__ float gs[64][64];
    __shared__ float es[64][64];
    int t = threadIdx.x;
    for (int i = t; i < 4096; i += 256) {
        int r = i >> 6, c = i & 63;
        gs[r][c] = gf[(b * 64 + r) * 256 + h * 64 + c];
        es[r][c] = ef1[i];
    }
    __syncthreads();
    int d0 = (t >> 4) << 2, m0 = (t & 15) << 2;
    float acc[4][4] = {};
    for (int n1 = 0; n1 < 64; n1++) {
        float4 a = *(const float4*)&gs[n1][d0];
        float4 v = *(const float4*)&es[n1][m0];
        float av[4] = {a.x, a.y, a.z, a.w};
        float bv[4] = {v.x, v.y, v.z, v.w};
        #pragma unroll
        for (int i = 0; i < 4; i++)
            #pragma unroll
            for (int j = 0; j < 4; j++)
                acc[i][j] += av[i] * bv[j];
    }
    float* o = g_gvp + (size_t)bh * 4096;
    #pragma unroll
    for (int i = 0; i < 4; i++)
        #pragma unroll
        for (int j = 0; j < 4; j++)
            o[(d0 + i) * 64 + m0 + j] = acc[i][j];
}

// split + transpose vp: g_vph[bh][m][k] = split(g_gvp[bh][k][m])
__global__ void k_prep_vp() {
    int i = blockIdx.x * 256 + threadIdx.x;      // 262144
    int bh = i >> 12, rem = i & 4095, k = rem >> 6, m = rem & 63;
    size_t o = (size_t)bh * 4096 + m * 64 + k;
    split2(g_gvp[i], g_vph[o], g_vpl[o]);
}

// ---------------------------------------------------------------------------
// skip_kp partials (wmma bf16x3), 32-row K-steps + skip prefetch.
// part[chunk][b][c][k] = sum_{n in chunk} skip[b,n,c]*EF2[n,k]
// ---------------------------------------------------------------------------
__global__ void __launch_bounds__(256) k_skp(const float* __restrict__ skip) {
    int chunk = blockIdx.x, ct = blockIdx.y, b = blockIdx.z;
    __shared__ __nv_bfloat16 ash[32][72], asl[32][72];   // [n][c]
    __shared__ __nv_bfloat16 bsh[32][72], bsl[32][72];   // [n][k]
    int t = threadIdx.x, w = t >> 5;

    wmma::fragment<wmma::accumulator, 16, 16, 16, float> acc[2];
    wmma::fill_fragment(acc[0], 0.f);
    wmma::fill_fragment(acc[1], 0.f);
    int c0 = (w >> 1) * 16;
    int kc = (w & 1) * 32;

    // loader indices
    int f0 = t, f1 = t + 256;                       // float4 indices (512 total)
    int r0s = f0 >> 4, c40 = f0 & 15;
    int r1s = f1 >> 4, c41 = f1 & 15;
    int er = t >> 3, ek8 = (t & 7) * 8;             // ef2 row / k-offset

    size_t sbase = ((size_t)b * NN + chunk * 1024) * NC + ct * 64;
    float4 pf0 = *(const float4*)&skip[sbase + (size_t)r0s * NC + c40 * 4];
    float4 pf1 = *(const float4*)&skip[sbase + (size_t)r1s * NC + c41 * 4];

    for (int ns = 0; ns < 32; ns++) {
        int n0 = chunk * 1024 + ns * 32;
        // store current regs -> smem (split + packed bf16x2 stores)
        {
            __nv_bfloat16 hx, lx, hy, ly, hz, lz, hw, lw;
            split2(pf0.x, hx, lx); split2(pf0.y, hy, ly);
            split2(pf0.z, hz, lz); split2(pf0.w, hw, lw);
            *(unsigned*)&ash[r0s][c40 * 4]     = pack_bf16(hx, hy);
            *(unsigned*)&ash[r0s][c40 * 4 + 2] = pack_bf16(hz, hw);
            *(unsigned*)&asl[r0s][c40 * 4]     = pack_bf16(lx, ly);
            *(unsigned*)&asl[r0s][c40 * 4 + 2] = pack_bf16(lz, lw);
            split2(pf1.x, hx, lx); split2(pf1.y, hy, ly);
            split2(pf1.z, hz, lz); split2(pf1.w, hw, lw);
            *(unsigned*)&ash[r1s][c41 * 4]     = pack_bf16(hx, hy);
            *(unsigned*)&ash[r1s][c41 * 4 + 2] = pack_bf16(hz, hw);
            *(unsigned*)&asl[r1s][c41 * 4]     = pack_bf16(lx, ly);
            *(unsigned*)&asl[r1s][c41 * 4 + 2] = pack_bf16(lz, lw);
        }
        *(uint4*)&bsh[er][ek8] = *(const uint4*)&g_ef2h[(size_t)(n0 + er) * 64 + ek8];
        *(uint4*)&bsl[er][ek8] = *(const uint4*)&g_ef2l[(size_t)(n0 + er) * 64 + ek8];

        // prefetch next step's skip
        if (ns < 31) {
            size_t nb = sbase + (size_t)(ns + 1) * 32 * NC;
            pf0 = *(const float4*)&skip[nb + (size_t)r0s * NC + c40 * 4];
            pf1 = *(const float4*)&skip[nb + (size_t)r1s * NC + c41 * 4];
        }
        __syncthreads();

        #pragma unroll
        for (int hf = 0; hf < 2; hf++) {
            wmma::fragment<wmma::matrix_a, 16, 16, 16, __nv_bfloat16, wmma::col_major> ah, al;
            wmma::load_matrix_sync(ah, &ash[hf * 16][c0], 72);
            wmma::load_matrix_sync(al, &asl[hf * 16][c0], 72);
            #pragma unroll
            for (int kt = 0; kt < 2; kt++) {
                wmma::fragment<wmma::matrix_b, 16, 16, 16, __nv_bfloat16, wmma::row_major> bh, bl;
                wmma::load_matrix_sync(bh, &bsh[hf * 16][kc + kt * 16], 72);
                wmma::load_matrix_sync(bl, &bsl[hf * 16][kc + kt * 16], 72);
                wmma::mma_sync(acc[kt], ah, bh, acc[kt]);
                wmma::mma_sync(acc[kt], ah, bl, acc[kt]);
                wmma::mma_sync(acc[kt], al, bh, acc[kt]);
            }
        }
        __syncthreads();
    }
    float* p = g_part + (((size_t)chunk * NB + b) * NC + ct * 64 + c0) * 64 + kc;
    wmma::store_matrix_sync(p, acc[0], 64, wmma::mem_row_major);
    wmma::store_matrix_sync(p + 16, acc[1], 64, wmma::mem_row_major);
}

// ---------------------------------------------------------------------------
// Reduce partials (fixed order), split + TRANSPOSE into g_skp[b][h][k][d]
// ---------------------------------------------------------------------------
__global__ void k_reduce() {
    int i = blockIdx.x * 256 + threadIdx.x;      // over NB*NC*NK = 262144
    float s = 0.f;
    #pragma unroll
    for (int c = 0; c < NCHUNK; c++) s += g_part[(size_t)c * (NB * NC * NK) + i];
    int b = i >> 14, rem = i & 16383, c = rem >> 6, k = rem & 63;
    int h = c >> 6, d = c & 63;
    size_t o = (((size_t)(b * NH + h) * 64 + k) * 64) + d;
    split2(s, g_skph[o], g_skpl[o]);
}

// ---------------------------------------------------------------------------
// Fused attention, PTX mma register pipeline (FA2-style P-in-register):
// logits (acc regs) -> softmax (reg + shfl) -> P packed to A-frags -> values
// Block: 256 threads / 8 warps; warp = 16 rows x 64 cols. 2 barriers total.
// ---------------------------------------------------------------------------
__global__ void __launch_bounds__(256) k_attn(
    const float* __restrict__ outq, const float* __restrict__ temp,
    float* __restrict__ x)
{
    extern __shared__ char smbuf[];
    __nv_bfloat16* qh  = (__nv_bfloat16*)smbuf;          // 128x72
    __nv_bfloat16* ql  = qh + 128 * 72;                  // 128x72
    __nv_bfloat16* sph = ql + 128 * 72;                  // 64x72  skpT [k][d]
    __nv_bfloat16* spl = sph + 64 * 72;
    __nv_bfloat16* vph = spl + 64 * 72;                  // 64x72  vpT  [m][k]
    __nv_bfloat16* vpl = vph + 64 * 72;
    float* lg = (float*)smbuf;                           // overlays qh+ql (out staging)

    int nt = blockIdx.x, h = blockIdx.y, b = blockIdx.z;
    int t = threadIdx.x, w = t >> 5, lane = t & 31;
    int gid = lane >> 2, tid = lane & 3;
    int r0 = w * 16;

    // cooperative loads
    {
        size_t base = (size_t)(b * NH + h) * 4096;
        for (int i = t; i < 512; i += 256) {
            int r = i >> 3, k8 = (i & 7) * 8;
            *(uint4*)&sph[r * 72 + k8] = *(const uint4*)&g_skph[base + r * 64 + k8];
            *(uint4*)&spl[r * 72 + k8] = *(const uint4*)&g_skpl[base + r * 64 + k8];
            *(uint4*)&vph[r * 72 + k8] = *(const uint4*)&g_vph[base + r * 64 + k8];
            *(uint4*)&vpl[r * 72 + k8] = *(const uint4*)&g_vpl[base + r * 64 + k8];
        }
        int r = t >> 1, c0 = (t & 1) * 32;
        const float* qrow = outq + ((size_t)b * NN + nt * 128 + r) * NC + h * 64 + c0;
        #pragma unroll
        for (int j = 0; j < 8; j++) {
            float4 v = *(const float4*)&qrow[j * 4];
            int cc = c0 + j * 4;
            __nv_bfloat16 hx, lx, hy, ly, hz, lz, hw, lw;
            split2(v.x, hx, lx); split2(v.y, hy, ly);
            split2(v.z, hz, lz); split2(v.w, hw, lw);
            *(unsigned*)&qh[r * 72 + cc]     = pack_bf16(hx, hy);
            *(unsigned*)&qh[r * 72 + cc + 2] = pack_bf16(hz, hw);
            *(unsigned*)&ql[r * 72 + cc]     = pack_bf16(lx, ly);
            *(unsigned*)&ql[r * 72 + cc + 2] = pack_bf16(lz, lw);
        }
    }
    __syncthreads();

    // ---- logits: acc[kb] = q(16x64) @ skp(64 x kb-block-of-8) ----
    float acc[8][4];
    #pragma unroll
    for (int kb = 0; kb < 8; kb++)
        #pragma unroll
        for (int i = 0; i < 4; i++) acc[kb][i] = 0.f;

    #pragma unroll
    for (int dt = 0; dt < 4; dt++) {
        unsigned ah[4], al[4];
        int qb = (r0 + gid) * 72 + dt * 16 + 2 * tid;
        ah[0] = *(unsigned*)&qh[qb];
        ah[1] = *(unsigned*)&qh[qb + 8 * 72];
        ah[2] = *(unsigned*)&qh[qb + 8];
        ah[3] = *(unsigned*)&qh[qb + 8 * 72 + 8];
        al[0] = *(unsigned*)&ql[qb];
        al[1] = *(unsigned*)&ql[qb + 8 * 72];
        al[2] = *(unsigned*)&ql[qb + 8];
        al[3] = *(unsigned*)&ql[qb + 8 * 72 + 8];
        #pragma unroll
        for (int kb = 0; kb < 8; kb++) {
            unsigned bh[2], bl[2];
            int sb = (kb * 8 + gid) * 72 + dt * 16 + 2 * tid;
            bh[0] = *(unsigned*)&sph[sb];
            bh[1] = *(unsigned*)&sph[sb + 8];
            bl[0] = *(unsigned*)&spl[sb];
            bl[1] = *(unsigned*)&spl[sb + 8];
            mma16816(acc[kb], ah, bh);
            mma16816(acc[kb], ah, bl);
            mma16816(acc[kb], al, bh);
        }
    }

    // ---- softmax in registers (rows gid and gid+8; 4-lane shfl groups) ----
    float tempv = temp[h];
    #pragma unroll
    for (int kb = 0; kb < 8; kb++)
        #pragma unroll
        for (int i = 0; i < 4; i++) acc[kb][i] *= tempv;

    float mx0 = -1e30f, mx1 = -1e30f;
    #pragma unroll
    for (int kb = 0; kb < 8; kb++) {
        mx0 = fmaxf(mx0, fmaxf(acc[kb][0], acc[kb][1]));
        mx1 = fmaxf(mx1, fmaxf(acc[kb][2], acc[kb][3]));
    }
    mx0 = fmaxf(mx0, __shfl_xor_sync(0xffffffffu, mx0, 1));
    mx0 = fmaxf(mx0, __shfl_xor_sync(0xffffffffu, mx0, 2));
    mx1 = fmaxf(mx1, __shfl_xor_sync(0xffffffffu, mx1, 1));
    mx1 = fmaxf(mx1, __shfl_xor_sync(0xffffffffu, mx1, 2));

    float sum0 = 0.f, sum1 = 0.f;
    #pragma unroll
    for (int kb = 0; kb < 8; kb++) {
        acc[kb][0] = __expf(acc[kb][0] - mx0);
        acc[kb][1] = __expf(acc[kb][1] - mx0);
        acc[kb][2] = __expf(acc[kb][2] - mx1);
        acc[kb][3] = __expf(acc[kb][3] - mx1);
        sum0 += acc[kb][0] + acc[kb][1];
        sum1 += acc[kb][2] + acc[kb][3];
    }
    sum0 += __shfl_xor_sync(0xffffffffu, sum0, 1);
    sum0 += __shfl_xor_sync(0xffffffffu, sum0, 2);
    sum1 += __shfl_xor_sync(0xffffffffu, sum1, 1);
    sum1 += __shfl_xor_sync(0xffffffffu, sum1, 2);
    float inv0 = 1.f / sum0, inv1 = 1.f / sum1;

    // ---- pack P into bf16x3 A-fragments (C-frag -> A-frag identity) ----
    unsigned pah[4][4], pal[4][4];
    #pragma unroll
    for (int kt = 0; kt < 4; kt++) {
        #pragma unroll
        for (int half = 0; half < 2; half++) {
            int kb = 2 * kt + half;
            float p0 = acc[kb][0] * inv0, p1 = acc[kb][1] * inv0;
            float p2 = acc[kb][2] * inv1, p3 = acc[kb][3] * inv1;
            __nv_bfloat16 h0, l0, h1, l1, h2, l2, h3, l3;
            split2(p0, h0, l0); split2(p1, h1, l1);
            split2(p2, h2, l2); split2(p3, h3, l3);
            pah[kt][half * 2]     = pack_bf16(h0, h1);
            pah[kt][half * 2 + 1] = pack_bf16(h2, h3);
            pal[kt][half * 2]     = pack_bf16(l0, l1);
            pal[kt][half * 2 + 1] = pack_bf16(l2, l3);
        }
    }

    // ---- values: acc2[mb] = P(16x64) @ vp(64 x mb-block-of-8) ----
    float acc2[8][4];
    #pragma unroll
    for (int mb = 0; mb < 8; mb++)
        #pragma unroll
        for (int i = 0; i < 4; i++) acc2[mb][i] = 0.f;

    #pragma unroll
    for (int kt = 0; kt < 4; kt++) {
        #pragma unroll
        for (int mb = 0; mb < 8; mb++) {
            unsigned bh[2], bl[2];
            int vb = (mb * 8 + gid) * 72 + kt * 16 + 2 * tid;
            bh[0] = *(unsigned*)&vph[vb];
            bh[1] = *(unsigned*)&vph[vb + 8];
            bl[0] = *(unsigned*)&vpl[vb];
            bl[1] = *(unsigned*)&vpl[vb + 8];
            mma16816(acc2[mb], pah[kt], bh);
            mma16816(acc2[mb], pah[kt], bl);
            mma16816(acc2[mb], pal[kt], bh);
        }
    }

    // stage output in smem (overlays dead q buffers; warp-local rows)
    #pragma unroll
    for (int mb = 0; mb < 8; mb++) {
        int ob = (r0 + gid) * 72 + mb * 8 + 2 * tid;
        *(float2*)&lg[ob]          = make_float2(acc2[mb][0], acc2[mb][1]);
        *(float2*)&lg[ob + 8 * 72] = make_float2(acc2[mb][2], acc2[mb][3]);
    }
    __syncthreads();

    // permuted writeback: x[b, m*(H*N) + h*N + n], coalesced over n
    {
        int m = t >> 2, rq = (t & 3) * 32;
        float* od = x + (size_t)b * (NN * NC) + (size_t)m * (NH * NN) + (size_t)h * NN + nt * 128;
        #pragma unroll
        for (int r = rq; r < rq + 32; r += 4) {
            float4 o;
            o.x = lg[(r + 0) * 72 + m];
            o.y = lg[(r + 1) * 72 + m];
            o.z = lg[(r + 2) * 72 + m];
            o.w = lg[(r + 3) * 72 + m];
            *(float4*)&od[r] = o;
        }
    }
}

// ---------------------------------------------------------------------------
extern "C" void kernel_launch(void* const* d_in, const int* in_sizes, int n_in,
                              void* d_out, int out_size) {
    const float* skip = (const float*)d_in[0];
    const float* outq = (const float*)d_in[1];
    const float* gf   = (const float*)d_in[2];
    const float* ef1  = (const float*)d_in[3];
    const float* ef2  = (const float*)d_in[4];
    const float* temp = (const float*)d_in[5];
    float* x = (float*)d_out;

    cudaFuncSetAttribute(k_attn, cudaFuncAttributeMaxDynamicSharedMemorySize, 73728);

    k_prep_ef2<<<(NN * NK) / 256, 256>>>(ef2);
    k_gvp<<<NB * NH, 256>>>(gf, ef1);
    k_prep_vp<<<(NB * NH * 64 * 64) / 256, 256>>>();
    k_skp<<<dim3(NCHUNK, 4, NB), 256>>>(skip);
    k_reduce<<<(NB * NC * NK) / 256, 256>>>();
    k_attn<<<dim3(NN / 128, NH, NB), 256, 73728>>>(outq, temp, x);
}

// round 4
// speedup vs baseline: 1.4568x; 1.4568x over previous
#include <cuda_runtime.h>
#include <cuda_bf16.h>
#include <mma.h>
#include <math.h>

using namespace nvcuda;

#define NB 16
#define NN 8192
#define NC 256
#define NH 4
#define NK 64
#define NCHUNK 8

// Scratch (__device__ globals; no allocations allowed)
static __device__ float g_part[NCHUNK * NB * NC * NK];          // 8 MB partials
static __device__ float g_gvp[NB * NH * 64 * 64];               // fp32 global_vp [k][m]
static __device__ __nv_bfloat16 g_ef2h[NN * NK], g_ef2l[NN * NK];           // [n][k]
static __device__ __nv_bfloat16 g_skph[NB * NC * NK], g_skpl[NB * NC * NK]; // [b][h][k][d]
static __device__ __nv_bfloat16 g_vph[NB * NH * 64 * 64], g_vpl[NB * NH * 64 * 64]; // [b][h][m][k]

__device__ __forceinline__ void split2(float v, __nv_bfloat16& hi, __nv_bfloat16& lo) {
    hi = __float2bfloat16_rn(v);
    lo = __float2bfloat16_rn(v - __bfloat162float(hi));
}

// mma.sync m16n8k16 row.col bf16 -> f32, D += A*B
__device__ __forceinline__ void mma16816(float* c, const unsigned* a, const unsigned* b) {
    asm volatile(
        "mma.sync.aligned.m16n8k16.row.col.f32.bf16.bf16.f32 "
        "{%0,%1,%2,%3}, {%4,%5,%6,%7}, {%8,%9}, {%0,%1,%2,%3};"
        : "+f"(c[0]), "+f"(c[1]), "+f"(c[2]), "+f"(c[3])
        : "r"(a[0]), "r"(a[1]), "r"(a[2]), "r"(a[3]), "r"(b[0]), "r"(b[1]));
}

__device__ __forceinline__ void ldsm_x4(unsigned* r, const void* p) {
    unsigned a = (unsigned)__cvta_generic_to_shared(p);
    asm volatile("ldmatrix.sync.aligned.m8n8.x4.shared.b16 {%0,%1,%2,%3}, [%4];"
        : "=r"(r[0]), "=r"(r[1]), "=r"(r[2]), "=r"(r[3]) : "r"(a));
}

__device__ __forceinline__ unsigned pack_bf16(__nv_bfloat16 lo, __nv_bfloat16 hi) {
    __nv_bfloat162 p = __halves2bfloat162(lo, hi);   // .x = low half
    return *(unsigned*)&p;
}

// ---------------------------------------------------------------------------
__global__ void k_prep_ef2(const float* __restrict__ ef2) {
    int i = blockIdx.x * 256 + threadIdx.x;
    split2(ef2[i], g_ef2h[i], g_ef2l[i]);
}

// global_vp (fp32, tiny): g_gvp[bh][d1][m] = sum_n1 gf[b,n1,h*64+d1]*EF1[n1,m]
__global__ void k_gvp(const float* __restrict__ gf, const float* __restrict__ ef1) {
    int bh = blockIdx.x, b = bh >> 2, h = bh & 3;
    __shared__ float gs[64][64];
    __shared__ float es[64][64];
    int t = threadIdx.x;
    for (int i = t; i < 4096; i += 256) {
        int r = i >> 6, c = i & 63;
        gs[r][c] = gf[(b * 64 + r) * 256 + h * 64 + c];
        es[r][c] = ef1[i];
    }
    __syncthreads();
    int d0 = (t >> 4) << 2, m0 = (t & 15) << 2;
    float acc[4][4] = {};
    for (int n1 = 0; n1 < 64; n1++) {
        float4 a = *(const float4*)&gs[n1][d0];
        float4 v = *(const float4*)&es[n1][m0];
        float av[4] = {a.x, a.y, a.z, a.w};
        float bv[4] = {v.x, v.y, v.z, v.w};
        #pragma unroll
        for (int i = 0; i < 4; i++)
            #pragma unroll
            for (int j = 0; j < 4; j++)
                acc[i][j] += av[i] * bv[j];
    }
    float* o = g_gvp + (size_t)bh * 4096;
    #pragma unroll
    for (int i = 0; i < 4; i++)
        #pragma unroll
        for (int j = 0; j < 4; j++)
            o[(d0 + i) * 64 + m0 + j] = acc[i][j];
}

// split + transpose vp: g_vph[bh][m][k] = split(g_gvp[bh][k][m])
__global__ void k_prep_vp() {
    int i = blockIdx.x * 256 + threadIdx.x;      // 262144
    int bh = i >> 12, rem = i & 4095, k = rem >> 6, m = rem & 63;
    size_t o = (size_t)bh * 4096 + m * 64 + k;
    split2(g_gvp[i], g_vph[o], g_vpl[o]);
}

// ---------------------------------------------------------------------------
// skip_kp partials (wmma bf16x3), 16-row K-steps (round-2 proven version).
// part[chunk][b][c][k] = sum_{n in chunk} skip[b,n,c]*EF2[n,k]
// ---------------------------------------------------------------------------
__global__ void __launch_bounds__(256) k_skp(const float* __restrict__ skip) {
    int chunk = blockIdx.x, ct = blockIdx.y, b = blockIdx.z;
    __shared__ __nv_bfloat16 ash[16][72], asl[16][72];   // [n][c]
    __shared__ __nv_bfloat16 bsh[16][72], bsl[16][72];   // [n][k]
    int t = threadIdx.x, w = t >> 5;

    wmma::fragment<wmma::accumulator, 16, 16, 16, float> acc[2];
    wmma::fill_fragment(acc[0], 0.f);
    wmma::fill_fragment(acc[1], 0.f);
    int c0 = (w >> 1) * 16;
    int kc = (w & 1) * 32;

    int lr = t >> 4, lc4 = (t & 15) * 4;                 // skip: 16x64 fp32
    int er = (t & 127) >> 3, ek8 = (t & 7) * 8;          // ef2: 16x64 bf16 (hi or lo)

    for (int ns = 0; ns < 64; ns++) {
        int n0 = chunk * 1024 + ns * 16;
        float4 v = *(const float4*)&skip[((size_t)b * NN + n0 + lr) * NC + ct * 64 + lc4];
        if (t < 128)
            *(uint4*)&bsh[er][ek8] = *(const uint4*)&g_ef2h[(size_t)(n0 + er) * 64 + ek8];
        else
            *(uint4*)&bsl[er][ek8] = *(const uint4*)&g_ef2l[(size_t)(n0 + er) * 64 + ek8];
        split2(v.x, ash[lr][lc4 + 0], asl[lr][lc4 + 0]);
        split2(v.y, ash[lr][lc4 + 1], asl[lr][lc4 + 1]);
        split2(v.z, ash[lr][lc4 + 2], asl[lr][lc4 + 2]);
        split2(v.w, ash[lr][lc4 + 3], asl[lr][lc4 + 3]);
        __syncthreads();

        wmma::fragment<wmma::matrix_a, 16, 16, 16, __nv_bfloat16, wmma::col_major> ah, al;
        wmma::load_matrix_sync(ah, &ash[0][c0], 72);
        wmma::load_matrix_sync(al, &asl[0][c0], 72);
        #pragma unroll
        for (int kt = 0; kt < 2; kt++) {
            wmma::fragment<wmma::matrix_b, 16, 16, 16, __nv_bfloat16, wmma::row_major> bh, bl;
            wmma::load_matrix_sync(bh, &bsh[0][kc + kt * 16], 72);
            wmma::load_matrix_sync(bl, &bsl[0][kc + kt * 16], 72);
            wmma::mma_sync(acc[kt], ah, bh, acc[kt]);
            wmma::mma_sync(acc[kt], ah, bl, acc[kt]);
            wmma::mma_sync(acc[kt], al, bh, acc[kt]);
        }
        __syncthreads();
    }
    float* p = g_part + (((size_t)chunk * NB + b) * NC + ct * 64 + c0) * 64 + kc;
    wmma::store_matrix_sync(p, acc[0], 64, wmma::mem_row_major);
    wmma::store_matrix_sync(p + 16, acc[1], 64, wmma::mem_row_major);
}

// ---------------------------------------------------------------------------
// Reduce partials (fixed order), split + TRANSPOSE into g_skp[b][h][k][d]
// ---------------------------------------------------------------------------
__global__ void k_reduce() {
    int i = blockIdx.x * 256 + threadIdx.x;      // over NB*NC*NK = 262144
    float s = 0.f;
    #pragma unroll
    for (int c = 0; c < NCHUNK; c++) s += g_part[(size_t)c * (NB * NC * NK) + i];
    int b = i >> 14, rem = i & 16383, c = rem >> 6, k = rem & 63;
    int h = c >> 6, d = c & 63;
    size_t o = (((size_t)(b * NH + h) * 64 + k) * 64) + d;
    split2(s, g_skph[o], g_skpl[o]);
}

// ---------------------------------------------------------------------------
// Fused attention: register softmax + P-in-registers, ALL fragment loads via
// ldmatrix.x4 (stride-72 rows are ldmatrix-conflict-free).
// Block: 256 threads / 8 warps; warp = 16 rows x 64 cols.
// ---------------------------------------------------------------------------
__global__ void __launch_bounds__(256) k_attn(
    const float* __restrict__ outq, const float* __restrict__ temp,
    float* __restrict__ x)
{
    extern __shared__ char smbuf[];
    __nv_bfloat16* qh  = (__nv_bfloat16*)smbuf;          // 128x72
    __nv_bfloat16* ql  = qh + 128 * 72;                  // 128x72
    __nv_bfloat16* sph = ql + 128 * 72;                  // 64x72  skpT [k][d]
    __nv_bfloat16* spl = sph + 64 * 72;
    __nv_bfloat16* vph = spl + 64 * 72;                  // 64x72  vpT  [m][k]
    __nv_bfloat16* vpl = vph + 64 * 72;
    float* lg = (float*)smbuf;                           // overlays qh+ql (out staging)

    int nt = blockIdx.x, h = blockIdx.y, b = blockIdx.z;
    int t = threadIdx.x, w = t >> 5, lane = t & 31;
    int gid = lane >> 2, tid = lane & 3;
    int r0 = w * 16;

    // ldmatrix lane address components
    int arow = lane & 15, acol8 = (lane >> 4) * 8;                 // A x4 pattern
    int brow = (lane & 7) + ((lane >> 4) << 3);                    // B x4 pattern
    int bcol8 = ((lane >> 3) & 1) * 8;

    // cooperative loads
    {
        size_t base = (size_t)(b * NH + h) * 4096;
        for (int i = t; i < 512; i += 256) {
            int r = i >> 3, k8 = (i & 7) * 8;
            *(uint4*)&sph[r * 72 + k8] = *(const uint4*)&g_skph[base + r * 64 + k8];
            *(uint4*)&spl[r * 72 + k8] = *(const uint4*)&g_skpl[base + r * 64 + k8];
            *(uint4*)&vph[r * 72 + k8] = *(const uint4*)&g_vph[base + r * 64 + k8];
            *(uint4*)&vpl[r * 72 + k8] = *(const uint4*)&g_vpl[base + r * 64 + k8];
        }
        int r = t >> 1, c0 = (t & 1) * 32;
        const float* qrow = outq + ((size_t)b * NN + nt * 128 + r) * NC + h * 64 + c0;
        #pragma unroll
        for (int j = 0; j < 8; j++) {
            float4 v = *(const float4*)&qrow[j * 4];
            int cc = c0 + j * 4;
            __nv_bfloat16 hx, lx, hy, ly, hz, lz, hw, lw;
            split2(v.x, hx, lx); split2(v.y, hy, ly);
            split2(v.z, hz, lz); split2(v.w, hw, lw);
            *(unsigned*)&qh[r * 72 + cc]     = pack_bf16(hx, hy);
            *(unsigned*)&qh[r * 72 + cc + 2] = pack_bf16(hz, hw);
            *(unsigned*)&ql[r * 72 + cc]     = pack_bf16(lx, ly);
            *(unsigned*)&ql[r * 72 + cc + 2] = pack_bf16(lz, lw);
        }
    }
    __syncthreads();

    // ---- logits: acc[kb] = q(16x64) @ skpT(64k x 64d)^T, kb = 8-col block ----
    float acc[8][4];
    #pragma unroll
    for (int kb = 0; kb < 8; kb++)
        #pragma unroll
        for (int i = 0; i < 4; i++) acc[kb][i] = 0.f;

    #pragma unroll
    for (int dt = 0; dt < 4; dt++) {
        unsigned ah[4], al[4];
        ldsm_x4(ah, &qh[(r0 + arow) * 72 + dt * 16 + acol8]);
        ldsm_x4(al, &ql[(r0 + arow) * 72 + dt * 16 + acol8]);
        #pragma unroll
        for (int p = 0; p < 4; p++) {            // p covers kb = 2p, 2p+1
            unsigned bh[4], bl[4];
            ldsm_x4(bh, &sph[(p * 16 + brow) * 72 + dt * 16 + bcol8]);
            ldsm_x4(bl, &spl[(p * 16 + brow) * 72 + dt * 16 + bcol8]);
            mma16816(acc[2 * p],     ah, bh);
            mma16816(acc[2 * p],     ah, bl);
            mma16816(acc[2 * p],     al, bh);
            mma16816(acc[2 * p + 1], ah, bh + 2);
            mma16816(acc[2 * p + 1], ah, bl + 2);
            mma16816(acc[2 * p + 1], al, bh + 2);
        }
    }

    // ---- softmax in registers (rows gid / gid+8; 4-lane shfl groups) ----
    float tempv = temp[h];
    #pragma unroll
    for (int kb = 0; kb < 8; kb++)
        #pragma unroll
        for (int i = 0; i < 4; i++) acc[kb][i] *= tempv;

    float mx0 = -1e30f, mx1 = -1e30f;
    #pragma unroll
    for (int kb = 0; kb < 8; kb++) {
        mx0 = fmaxf(mx0, fmaxf(acc[kb][0], acc[kb][1]));
        mx1 = fmaxf(mx1, fmaxf(acc[kb][2], acc[kb][3]));
    }
    mx0 = fmaxf(mx0, __shfl_xor_sync(0xffffffffu, mx0, 1));
    mx0 = fmaxf(mx0, __shfl_xor_sync(0xffffffffu, mx0, 2));
    mx1 = fmaxf(mx1, __shfl_xor_sync(0xffffffffu, mx1, 1));
    mx1 = fmaxf(mx1, __shfl_xor_sync(0xffffffffu, mx1, 2));

    float sum0 = 0.f, sum1 = 0.f;
    #pragma unroll
    for (int kb = 0; kb < 8; kb++) {
        acc[kb][0] = __expf(acc[kb][0] - mx0);
        acc[kb][1] = __expf(acc[kb][1] - mx0);
        acc[kb][2] = __expf(acc[kb][2] - mx1);
        acc[kb][3] = __expf(acc[kb][3] - mx1);
        sum0 += acc[kb][0] + acc[kb][1];
        sum1 += acc[kb][2] + acc[kb][3];
    }
    sum0 += __shfl_xor_sync(0xffffffffu, sum0, 1);
    sum0 += __shfl_xor_sync(0xffffffffu, sum0, 2);
    sum1 += __shfl_xor_sync(0xffffffffu, sum1, 1);
    sum1 += __shfl_xor_sync(0xffffffffu, sum1, 2);
    float inv0 = 1.f / sum0, inv1 = 1.f / sum1;

    // ---- pack P into bf16x3 A-fragments (C-frag -> A-frag identity) ----
    unsigned pah[4][4], pal[4][4];
    #pragma unroll
    for (int kt = 0; kt < 4; kt++) {
        #pragma unroll
        for (int half = 0; half < 2; half++) {
            int kb = 2 * kt + half;
            float p0 = acc[kb][0] * inv0, p1 = acc[kb][1] * inv0;
            float p2 = acc[kb][2] * inv1, p3 = acc[kb][3] * inv1;
            __nv_bfloat16 h0, l0, h1, l1, h2, l2, h3, l3;
            split2(p0, h0, l0); split2(p1, h1, l1);
            split2(p2, h2, l2); split2(p3, h3, l3);
            pah[kt][half * 2]     = pack_bf16(h0, h1);
            pah[kt][half * 2 + 1] = pack_bf16(h2, h3);
            pal[kt][half * 2]     = pack_bf16(l0, l1);
            pal[kt][half * 2 + 1] = pack_bf16(l2, l3);
        }
    }

    // ---- values: acc2[mb] = P(16x64) @ vpT(64m x 64k)^T ----
    float acc2[8][4];
    #pragma unroll
    for (int mb = 0; mb < 8; mb++)
        #pragma unroll
        for (int i = 0; i < 4; i++) acc2[mb][i] = 0.f;

    #pragma unroll
    for (int kt = 0; kt < 4; kt++) {
        #pragma unroll
        for (int p = 0; p < 4; p++) {            // p covers mb = 2p, 2p+1
            unsigned bh[4], bl[4];
            ldsm_x4(bh, &vph[(p * 16 + brow) * 72 + kt * 16 + bcol8]);
            ldsm_x4(bl, &vpl[(p * 16 + brow) * 72 + kt * 16 + bcol8]);
            mma16816(acc2[2 * p],     pah[kt], bh);
            mma16816(acc2[2 * p],     pah[kt], bl);
            mma16816(acc2[2 * p],     pal[kt], bh);
            mma16816(acc2[2 * p + 1], pah[kt], bh + 2);
            mma16816(acc2[2 * p + 1], pah[kt], bl + 2);
            mma16816(acc2[2 * p + 1], pal[kt], bh + 2);
        }
    }

    // all q reads done block-wide before overlay write
    __syncthreads();

    // stage output in smem (overlays dead q buffers)
    #pragma unroll
    for (int mb = 0; mb < 8; mb++) {
        int ob = (r0 + gid) * 72 + mb * 8 + 2 * tid;
        *(float2*)&lg[ob]          = make_float2(acc2[mb][0], acc2[mb][1]);
        *(float2*)&lg[ob + 8 * 72] = make_float2(acc2[mb][2], acc2[mb][3]);
    }
    __syncthreads();

    // permuted writeback: x[b, m*(H*N) + h*N + n], coalesced over n
    {
        int m = t >> 2, rq = (t & 3) * 32;
        float* od = x + (size_t)b * (NN * NC) + (size_t)m * (NH * NN) + (size_t)h * NN + nt * 128;
        #pragma unroll
        for (int r = rq; r < rq + 32; r += 4) {
            float4 o;
            o.x = lg[(r + 0) * 72 + m];
            o.y = lg[(r + 1) * 72 + m];
            o.z = lg[(r + 2) * 72 + m];
            o.w = lg[(r + 3) * 72 + m];
            *(float4*)&od[r] = o;
        }
    }
}

// ---------------------------------------------------------------------------
extern "C" void kernel_launch(void* const* d_in, const int* in_sizes, int n_in,
                              void* d_out, int out_size) {
    const float* skip = (const float*)d_in[0];
    const float* outq = (const float*)d_in[1];
    const float* gf   = (const float*)d_in[2];
    const float* ef1  = (const float*)d_in[3];
    const float* ef2  = (const float*)d_in[4];
    const float* temp = (const float*)d_in[5];
    float* x = (float*)d_out;

    cudaFuncSetAttribute(k_attn, cudaFuncAttributeMaxDynamicSharedMemorySize, 73728);

    k_prep_ef2<<<(NN * NK) / 256, 256>>>(ef2);
    k_gvp<<<NB * NH, 256>>>(gf, ef1);
    k_prep_vp<<<(NB * NH * 64 * 64) / 256, 256>>>();
    k_skp<<<dim3(NCHUNK, 4, NB), 256>>>(skip);
    k_reduce<<<(NB * NC * NK) / 256, 256>>>();
    k_attn<<<dim3(NN / 128, NH, NB), 256, 73728>>>(outq, temp, x);
}

// round 5
// speedup vs baseline: 1.5657x; 1.0747x over previous
#include <cuda_runtime.h>
#include <cuda_bf16.h>
#include <mma.h>
#include <math.h>

using namespace nvcuda;

#define NB 16
#define NN 8192
#define NC 256
#define NH 4
#define NK 64
#define NCHUNK 8

// Scratch (__device__ globals; no allocations allowed)
static __device__ float g_part[NCHUNK * NB * NC * NK];          // 32 MB partials
static __device__ float g_gvp[NB * NH * 64 * 64];               // fp32 global_vp [k][m]
static __device__ __nv_bfloat16 g_ef2h[NN * NK], g_ef2l[NN * NK];           // [n][k]
static __device__ __nv_bfloat16 g_skph[NB * NC * NK], g_skpl[NB * NC * NK]; // [b][h][k][d]
static __device__ __nv_bfloat16 g_vph[NB * NH * 64 * 64], g_vpl[NB * NH * 64 * 64]; // [b][h][m][k]

__device__ __forceinline__ void split2(float v, __nv_bfloat16& hi, __nv_bfloat16& lo) {
    hi = __float2bfloat16_rn(v);
    lo = __float2bfloat16_rn(v - __bfloat162float(hi));
}

// mma.sync m16n8k16 row.col bf16 -> f32, D += A*B
__device__ __forceinline__ void mma16816(float* c, const unsigned* a, const unsigned* b) {
    asm volatile(
        "mma.sync.aligned.m16n8k16.row.col.f32.bf16.bf16.f32 "
        "{%0,%1,%2,%3}, {%4,%5,%6,%7}, {%8,%9}, {%0,%1,%2,%3};"
        : "+f"(c[0]), "+f"(c[1]), "+f"(c[2]), "+f"(c[3])
        : "r"(a[0]), "r"(a[1]), "r"(a[2]), "r"(a[3]), "r"(b[0]), "r"(b[1]));
}

__device__ __forceinline__ void ldsm_x4(unsigned* r, const void* p) {
    unsigned a = (unsigned)__cvta_generic_to_shared(p);
    asm volatile("ldmatrix.sync.aligned.m8n8.x4.shared.b16 {%0,%1,%2,%3}, [%4];"
        : "=r"(r[0]), "=r"(r[1]), "=r"(r[2]), "=r"(r[3]) : "r"(a));
}

__device__ __forceinline__ unsigned pack_bf16(__nv_bfloat16 lo, __nv_bfloat16 hi) {
    __nv_bfloat162 p = __halves2bfloat162(lo, hi);   // .x = low half
    return *(unsigned*)&p;
}

// ---------------------------------------------------------------------------
__global__ void k_prep_ef2(const float* __restrict__ ef2) {
    int i = blockIdx.x * 256 + threadIdx.x;
    split2(ef2[i], g_ef2h[i], g_ef2l[i]);
}

// global_vp (fp32, tiny): g_gvp[bh][d1][m] = sum_n1 gf[b,n1,h*64+d1]*EF1[n1,m]
__global__ void k_gvp(const float* __restrict__ gf, const float* __restrict__ ef1) {
    int bh = blockIdx.x, b = bh >> 2, h = bh & 3;
    __shared__ float gs[64][64];
    __shared__ float es[64][64];
    int t = threadIdx.x;
    for (int i = t; i < 4096; i += 256) {
        int r = i >> 6, c = i & 63;
        gs[r][c] = gf[(b * 64 + r) * 256 + h * 64 + c];
        es[r][c] = ef1[i];
    }
    __syncthreads();
    int d0 = (t >> 4) << 2, m0 = (t & 15) << 2;
    float acc[4][4] = {};
    for (int n1 = 0; n1 < 64; n1++) {
        float4 a = *(const float4*)&gs[n1][d0];
        float4 v = *(const float4*)&es[n1][m0];
        float av[4] = {a.x, a.y, a.z, a.w};
        float bv[4] = {v.x, v.y, v.z, v.w};
        #pragma unroll
        for (int i = 0; i < 4; i++)
            #pragma unroll
            for (int j = 0; j < 4; j++)
                acc[i][j] += av[i] * bv[j];
    }
    float* o = g_gvp + (size_t)bh * 4096;
    #pragma unroll
    for (int i = 0; i < 4; i++)
        #pragma unroll
        for (int j = 0; j < 4; j++)
            o[(d0 + i) * 64 + m0 + j] = acc[i][j];
}

// split + transpose vp: g_vph[bh][m][k] = split(g_gvp[bh][k][m])
__global__ void k_prep_vp() {
    int i = blockIdx.x * 256 + threadIdx.x;      // 262144
    int bh = i >> 12, rem = i & 4095, k = rem >> 6, m = rem & 63;
    size_t o = (size_t)bh * 4096 + m * 64 + k;
    split2(g_gvp[i], g_vph[o], g_vpl[o]);
}

// ---------------------------------------------------------------------------
// skip_kp partials (wmma bf16x3), 2-stage ping-pong, ONE barrier per K-step.
// part[chunk][b][c][k] = sum_{n in chunk} skip[b,n,c]*EF2[n,k]
// ---------------------------------------------------------------------------
__global__ void __launch_bounds__(256) k_skp(const float* __restrict__ skip) {
    int chunk = blockIdx.x, ct = blockIdx.y, b = blockIdx.z;
    __shared__ __nv_bfloat16 ash[2][16][72], asl[2][16][72];   // [stage][n][c]
    __shared__ __nv_bfloat16 bsh[2][16][72], bsl[2][16][72];   // [stage][n][k]
    int t = threadIdx.x, w = t >> 5;

    wmma::fragment<wmma::accumulator, 16, 16, 16, float> acc[2];
    wmma::fill_fragment(acc[0], 0.f);
    wmma::fill_fragment(acc[1], 0.f);
    int c0 = (w >> 1) * 16;
    int kc = (w & 1) * 32;

    int lr = t >> 4, lc4 = (t & 15) * 4;                 // skip: 16x64 fp32
    int er = (t & 127) >> 3, ek8 = (t & 7) * 8;          // ef2: 16x64 bf16 (hi/lo half)
    bool hiload = (t < 128);

    size_t sbase = ((size_t)b * NN + chunk * 1024) * NC + ct * 64 + lc4;
    size_t ebase = (size_t)(chunk * 1024 + er) * 64 + ek8;

    // prologue: stage 0
    float4 v = *(const float4*)&skip[sbase + (size_t)lr * NC];
    uint4 e = hiload ? *(const uint4*)&g_ef2h[ebase] : *(const uint4*)&g_ef2l[ebase];
    {
        split2(v.x, ash[0][lr][lc4 + 0], asl[0][lr][lc4 + 0]);
        split2(v.y, ash[0][lr][lc4 + 1], asl[0][lr][lc4 + 1]);
        split2(v.z, ash[0][lr][lc4 + 2], asl[0][lr][lc4 + 2]);
        split2(v.w, ash[0][lr][lc4 + 3], asl[0][lr][lc4 + 3]);
        if (hiload) *(uint4*)&bsh[0][er][ek8] = e;
        else        *(uint4*)&bsl[0][er][ek8] = e;
    }
    __syncthreads();

    for (int ns = 0; ns < 64; ns++) {
        int cur = ns & 1;
        // issue next step's global loads early (overlap with MMA)
        if (ns < 63) {
            v = *(const float4*)&skip[sbase + (size_t)((ns + 1) * 16 + lr) * NC];
            size_t eb = ebase + (size_t)(ns + 1) * 16 * 64;
            e = hiload ? *(const uint4*)&g_ef2h[eb] : *(const uint4*)&g_ef2l[eb];
        }

        wmma::fragment<wmma::matrix_a, 16, 16, 16, __nv_bfloat16, wmma::col_major> ah, al;
        wmma::load_matrix_sync(ah, &ash[cur][0][c0], 72);
        wmma::load_matrix_sync(al, &asl[cur][0][c0], 72);
        #pragma unroll
        for (int kt = 0; kt < 2; kt++) {
            wmma::fragment<wmma::matrix_b, 16, 16, 16, __nv_bfloat16, wmma::row_major> bh, bl;
            wmma::load_matrix_sync(bh, &bsh[cur][0][kc + kt * 16], 72);
            wmma::load_matrix_sync(bl, &bsl[cur][0][kc + kt * 16], 72);
            wmma::mma_sync(acc[kt], ah, bh, acc[kt]);
            wmma::mma_sync(acc[kt], ah, bl, acc[kt]);
            wmma::mma_sync(acc[kt], al, bh, acc[kt]);
        }

        if (ns < 63) {
            int nxt = cur ^ 1;
            split2(v.x, ash[nxt][lr][lc4 + 0], asl[nxt][lr][lc4 + 0]);
            split2(v.y, ash[nxt][lr][lc4 + 1], asl[nxt][lr][lc4 + 1]);
            split2(v.z, ash[nxt][lr][lc4 + 2], asl[nxt][lr][lc4 + 2]);
            split2(v.w, ash[nxt][lr][lc4 + 3], asl[nxt][lr][lc4 + 3]);
            if (hiload) *(uint4*)&bsh[nxt][er][ek8] = e;
            else        *(uint4*)&bsl[nxt][er][ek8] = e;
        }
        __syncthreads();
    }
    float* p = g_part + (((size_t)chunk * NB + b) * NC + ct * 64 + c0) * 64 + kc;
    wmma::store_matrix_sync(p, acc[0], 64, wmma::mem_row_major);
    wmma::store_matrix_sync(p + 16, acc[1], 64, wmma::mem_row_major);
}

// ---------------------------------------------------------------------------
// Reduce partials (fixed order), split + TRANSPOSE into g_skp[b][h][k][d]
// ---------------------------------------------------------------------------
__global__ void k_reduce() {
    int i = blockIdx.x * 256 + threadIdx.x;      // over NB*NC*NK = 262144
    float s = 0.f;
    #pragma unroll
    for (int c = 0; c < NCHUNK; c++) s += g_part[(size_t)c * (NB * NC * NK) + i];
    int b = i >> 14, rem = i & 16383, c = rem >> 6, k = rem & 63;
    int h = c >> 6, d = c & 63;
    size_t o = (((size_t)(b * NH + h) * 64 + k) * 64) + d;
    split2(s, g_skph[o], g_skpl[o]);
}

// ---------------------------------------------------------------------------
// Fused attention: q A-fragments loaded DIRECTLY from global (coalesced
// 32B sectors), B-fragments via ldmatrix; register softmax + P-in-registers.
// Block: 256 threads / 8 warps; processes 256 rows (2 tiles of 128).
// ---------------------------------------------------------------------------
__global__ void __launch_bounds__(256) k_attn(
    const float* __restrict__ outq, const float* __restrict__ temp,
    float* __restrict__ x)
{
    extern __shared__ char smbuf[];
    __nv_bfloat16* sph = (__nv_bfloat16*)smbuf;          // 64x72  skpT [k][d]
    __nv_bfloat16* spl = sph + 64 * 72;
    __nv_bfloat16* vph = spl + 64 * 72;                  // 64x72  vpT  [m][k]
    __nv_bfloat16* vpl = vph + 64 * 72;
    float* outb = (float*)(vpl + 64 * 72);               // 128x72 out staging

    int nt = blockIdx.x, h = blockIdx.y, b = blockIdx.z;
    int t = threadIdx.x, w = t >> 5, lane = t & 31;
    int gid = lane >> 2, tid = lane & 3;
    int r0 = w * 16;

    // ldmatrix lane address components (B x4 pattern)
    int brow = (lane & 7) + ((lane >> 4) << 3);
    int bcol8 = ((lane >> 3) & 1) * 8;

    // cooperative load of skp/vp tiles
    {
        size_t base = (size_t)(b * NH + h) * 4096;
        for (int i = t; i < 512; i += 256) {
            int r = i >> 3, k8 = (i & 7) * 8;
            *(uint4*)&sph[r * 72 + k8] = *(const uint4*)&g_skph[base + r * 64 + k8];
            *(uint4*)&spl[r * 72 + k8] = *(const uint4*)&g_skpl[base + r * 64 + k8];
            *(uint4*)&vph[r * 72 + k8] = *(const uint4*)&g_vph[base + r * 64 + k8];
            *(uint4*)&vpl[r * 72 + k8] = *(const uint4*)&g_vpl[base + r * 64 + k8];
        }
    }
    float tempv = temp[h];
    __syncthreads();

    #pragma unroll
    for (int tile = 0; tile < 2; tile++) {
        int rowbase = nt * 256 + tile * 128 + r0 + gid;
        const float* qr0 = outq + ((size_t)b * NN + rowbase) * NC + h * 64;
        const float* qr8 = qr0 + 8 * NC;

        // ---- logits ----
        float acc[8][4];
        #pragma unroll
        for (int kb = 0; kb < 8; kb++)
            #pragma unroll
            for (int i = 0; i < 4; i++) acc[kb][i] = 0.f;

        #pragma unroll
        for (int dt = 0; dt < 4; dt++) {
            // A fragments straight from global, split in registers
            float2 v00 = *(const float2*)&qr0[dt * 16 + 2 * tid];
            float2 v10 = *(const float2*)&qr8[dt * 16 + 2 * tid];
            float2 v01 = *(const float2*)&qr0[dt * 16 + 2 * tid + 8];
            float2 v11 = *(const float2*)&qr8[dt * 16 + 2 * tid + 8];
            unsigned ah[4], al[4];
            {
                __nv_bfloat16 ha, la, hb, lb;
                split2(v00.x, ha, la); split2(v00.y, hb, lb);
                ah[0] = pack_bf16(ha, hb); al[0] = pack_bf16(la, lb);
                split2(v10.x, ha, la); split2(v10.y, hb, lb);
                ah[1] = pack_bf16(ha, hb); al[1] = pack_bf16(la, lb);
                split2(v01.x, ha, la); split2(v01.y, hb, lb);
                ah[2] = pack_bf16(ha, hb); al[2] = pack_bf16(la, lb);
                split2(v11.x, ha, la); split2(v11.y, hb, lb);
                ah[3] = pack_bf16(ha, hb); al[3] = pack_bf16(la, lb);
            }
            #pragma unroll
            for (int p = 0; p < 4; p++) {            // p covers kb = 2p, 2p+1
                unsigned bh[4], bl[4];
                ldsm_x4(bh, &sph[(p * 16 + brow) * 72 + dt * 16 + bcol8]);
                ldsm_x4(bl, &spl[(p * 16 + brow) * 72 + dt * 16 + bcol8]);
                mma16816(acc[2 * p],     ah, bh);
                mma16816(acc[2 * p],     ah, bl);
                mma16816(acc[2 * p],     al, bh);
                mma16816(acc[2 * p + 1], ah, bh + 2);
                mma16816(acc[2 * p + 1], ah, bl + 2);
                mma16816(acc[2 * p + 1], al, bh + 2);
            }
        }

        // ---- softmax in registers (rows gid / gid+8; 4-lane shfl groups) ----
        #pragma unroll
        for (int kb = 0; kb < 8; kb++)
            #pragma unroll
            for (int i = 0; i < 4; i++) acc[kb][i] *= tempv;

        float mx0 = -1e30f, mx1 = -1e30f;
        #pragma unroll
        for (int kb = 0; kb < 8; kb++) {
            mx0 = fmaxf(mx0, fmaxf(acc[kb][0], acc[kb][1]));
            mx1 = fmaxf(mx1, fmaxf(acc[kb][2], acc[kb][3]));
        }
        mx0 = fmaxf(mx0, __shfl_xor_sync(0xffffffffu, mx0, 1));
        mx0 = fmaxf(mx0, __shfl_xor_sync(0xffffffffu, mx0, 2));
        mx1 = fmaxf(mx1, __shfl_xor_sync(0xffffffffu, mx1, 1));
        mx1 = fmaxf(mx1, __shfl_xor_sync(0xffffffffu, mx1, 2));

        float sum0 = 0.f, sum1 = 0.f;
        #pragma unroll
        for (int kb = 0; kb < 8; kb++) {
            acc[kb][0] = __expf(acc[kb][0] - mx0);
            acc[kb][1] = __expf(acc[kb][1] - mx0);
            acc[kb][2] = __expf(acc[kb][2] - mx1);
            acc[kb][3] = __expf(acc[kb][3] - mx1);
            sum0 += acc[kb][0] + acc[kb][1];
            sum1 += acc[kb][2] + acc[kb][3];
        }
        sum0 += __shfl_xor_sync(0xffffffffu, sum0, 1);
        sum0 += __shfl_xor_sync(0xffffffffu, sum0, 2);
        sum1 += __shfl_xor_sync(0xffffffffu, sum1, 1);
        sum1 += __shfl_xor_sync(0xffffffffu, sum1, 2);
        float inv0 = 1.f / sum0, inv1 = 1.f / sum1;

        // ---- pack P into bf16x3 A-fragments (C-frag -> A-frag identity) ----
        unsigned pah[4][4], pal[4][4];
        #pragma unroll
        for (int kt = 0; kt < 4; kt++) {
            #pragma unroll
            for (int half = 0; half < 2; half++) {
                int kb = 2 * kt + half;
                float p0 = acc[kb][0] * inv0, p1 = acc[kb][1] * inv0;
                float p2 = acc[kb][2] * inv1, p3 = acc[kb][3] * inv1;
                __nv_bfloat16 h0, l0, h1, l1, h2, l2, h3, l3;
                split2(p0, h0, l0); split2(p1, h1, l1);
                split2(p2, h2, l2); split2(p3, h3, l3);
                pah[kt][half * 2]     = pack_bf16(h0, h1);
                pah[kt][half * 2 + 1] = pack_bf16(h2, h3);
                pal[kt][half * 2]     = pack_bf16(l0, l1);
                pal[kt][half * 2 + 1] = pack_bf16(l2, l3);
            }
        }

        // ---- values: acc2[mb] = P(16x64) @ vpT(64m x 64k)^T ----
        float acc2[8][4];
        #pragma unroll
        for (int mb = 0; mb < 8; mb++)
            #pragma unroll
            for (int i = 0; i < 4; i++) acc2[mb][i] = 0.f;

        #pragma unroll
        for (int kt = 0; kt < 4; kt++) {
            #pragma unroll
            for (int p = 0; p < 4; p++) {        // p covers mb = 2p, 2p+1
                unsigned bh[4], bl[4];
                ldsm_x4(bh, &vph[(p * 16 + brow) * 72 + kt * 16 + bcol8]);
                ldsm_x4(bl, &vpl[(p * 16 + brow) * 72 + kt * 16 + bcol8]);
                mma16816(acc2[2 * p],     pah[kt], bh);
                mma16816(acc2[2 * p],     pah[kt], bl);
                mma16816(acc2[2 * p],     pal[kt], bh);
                mma16816(acc2[2 * p + 1], pah[kt], bh + 2);
                mma16816(acc2[2 * p + 1], pah[kt], bl + 2);
                mma16816(acc2[2 * p + 1], pal[kt], bh + 2);
            }
        }

        // stage output in smem
        #pragma unroll
        for (int mb = 0; mb < 8; mb++) {
            int ob = (r0 + gid) * 72 + mb * 8 + 2 * tid;
            *(float2*)&outb[ob]          = make_float2(acc2[mb][0], acc2[mb][1]);
            *(float2*)&outb[ob + 8 * 72] = make_float2(acc2[mb][2], acc2[mb][3]);
        }
        __syncthreads();

        // permuted writeback: x[b, m*(H*N) + h*N + n], coalesced over n
        {
            int m = t >> 2, rq = (t & 3) * 32;
            float* od = x + (size_t)b * (NN * NC) + (size_t)m * (NH * NN)
                          + (size_t)h * NN + nt * 256 + tile * 128;
            #pragma unroll
            for (int r = rq; r < rq + 32; r += 4) {
                float4 o;
                o.x = outb[(r + 0) * 72 + m];
                o.y = outb[(r + 1) * 72 + m];
                o.z = outb[(r + 2) * 72 + m];
                o.w = outb[(r + 3) * 72 + m];
                *(float4*)&od[r] = o;
            }
        }
        __syncthreads();   // protect outb reuse by next tile
    }
}

// ---------------------------------------------------------------------------
extern "C" void kernel_launch(void* const* d_in, const int* in_sizes, int n_in,
                              void* d_out, int out_size) {
    const float* skip = (const float*)d_in[0];
    const float* outq = (const float*)d_in[1];
    const float* gf   = (const float*)d_in[2];
    const float* ef1  = (const float*)d_in[3];
    const float* ef2  = (const float*)d_in[4];
    const float* temp = (const float*)d_in[5];
    float* x = (float*)d_out;

    cudaFuncSetAttribute(k_attn, cudaFuncAttributeMaxDynamicSharedMemorySize, 73728);

    k_prep_ef2<<<(NN * NK) / 256, 256>>>(ef2);
    k_gvp<<<NB * NH, 256>>>(gf, ef1);
    k_prep_vp<<<(NB * NH * 64 * 64) / 256, 256>>>();
    k_skp<<<dim3(NCHUNK, 4, NB), 256>>>(skip);
    k_reduce<<<(NB * NC * NK) / 256, 256>>>();
    k_attn<<<dim3(NN / 256, NH, NB), 256, 73728>>>(outq, temp, x);
}

// round 6
// speedup vs baseline: 1.5899x; 1.0155x over previous
#include <cuda_runtime.h>
#include <cuda_bf16.h>
#include <mma.h>
#include <math.h>

using namespace nvcuda;

#define NB 16
#define NN 8192
#define NC 256
#define NH 4
#define NK 64
#define NCHUNK 8

// Scratch (__device__ globals; no allocations allowed)
static __device__ float g_part[NCHUNK * NB * NC * NK];          // partials
static __device__ __nv_bfloat16 g_ef2h[NN * NK], g_ef2l[NN * NK];           // [n][k]
static __device__ __nv_bfloat16 g_skph[NB * NC * NK], g_skpl[NB * NC * NK]; // [b][h][k][d]
static __device__ __nv_bfloat16 g_vph[NB * NH * 64 * 64], g_vpl[NB * NH * 64 * 64]; // [b][h][m][k]

__device__ __forceinline__ void split2(float v, __nv_bfloat16& hi, __nv_bfloat16& lo) {
    hi = __float2bfloat16_rn(v);
    lo = __float2bfloat16_rn(v - __bfloat162float(hi));
}

// mma.sync m16n8k16 row.col bf16 -> f32, D += A*B
__device__ __forceinline__ void mma16816(float* c, const unsigned* a, const unsigned* b) {
    asm volatile(
        "mma.sync.aligned.m16n8k16.row.col.f32.bf16.bf16.f32 "
        "{%0,%1,%2,%3}, {%4,%5,%6,%7}, {%8,%9}, {%0,%1,%2,%3};"
        : "+f"(c[0]), "+f"(c[1]), "+f"(c[2]), "+f"(c[3])
        : "r"(a[0]), "r"(a[1]), "r"(a[2]), "r"(a[3]), "r"(b[0]), "r"(b[1]));
}

__device__ __forceinline__ void ldsm_x4(unsigned* r, const void* p) {
    unsigned a = (unsigned)__cvta_generic_to_shared(p);
    asm volatile("ldmatrix.sync.aligned.m8n8.x4.shared.b16 {%0,%1,%2,%3}, [%4];"
        : "=r"(r[0]), "=r"(r[1]), "=r"(r[2]), "=r"(r[3]) : "r"(a));
}

__device__ __forceinline__ unsigned pack_bf16(__nv_bfloat16 lo, __nv_bfloat16 hi) {
    __nv_bfloat162 p = __halves2bfloat162(lo, hi);   // .x = low half
    return *(unsigned*)&p;
}

__device__ __forceinline__ void cp_async16(void* smem, const void* gmem) {
    unsigned s = (unsigned)__cvta_generic_to_shared(smem);
    asm volatile("cp.async.cg.shared.global [%0], [%1], 16;" :: "r"(s), "l"(gmem));
}
__device__ __forceinline__ void cp_commit() { asm volatile("cp.async.commit_group;"); }
__device__ __forceinline__ void cp_wait0()  { asm volatile("cp.async.wait_group 0;" ::: "memory"); }

// ---------------------------------------------------------------------------
__global__ void k_prep_ef2(const float* __restrict__ ef2) {
    int i = blockIdx.x * 256 + threadIdx.x;
    split2(ef2[i], g_ef2h[i], g_ef2l[i]);
}

// global_vp (fp32, tiny), fused split + transpose epilogue:
// g_vph[bh][m][k=d1] = split(sum_n1 gf[b,n1,h*64+d1]*EF1[n1,m])
__global__ void k_gvp(const float* __restrict__ gf, const float* __restrict__ ef1) {
    int bh = blockIdx.x, b = bh >> 2, h = bh & 3;
    __shared__ float gs[64][64];
    __shared__ float es[64][64];
    int t = threadIdx.x;
    for (int i = t; i < 4096; i += 256) {
        int r = i >> 6, c = i & 63;
        gs[r][c] = gf[(b * 64 + r) * 256 + h * 64 + c];
        es[r][c] = ef1[i];
    }
    __syncthreads();
    int d0 = (t >> 4) << 2, m0 = (t & 15) << 2;
    float acc[4][4] = {};
    for (int n1 = 0; n1 < 64; n1++) {
        float4 a = *(const float4*)&gs[n1][d0];
        float4 v = *(const float4*)&es[n1][m0];
        float av[4] = {a.x, a.y, a.z, a.w};
        float bv[4] = {v.x, v.y, v.z, v.w};
        #pragma unroll
        for (int i = 0; i < 4; i++)
            #pragma unroll
            for (int j = 0; j < 4; j++)
                acc[i][j] += av[i] * bv[j];
    }
    size_t base = (size_t)bh * 4096;
    #pragma unroll
    for (int i = 0; i < 4; i++)
        #pragma unroll
        for (int j = 0; j < 4; j++) {
            __nv_bfloat16 hi, lo;
            split2(acc[i][j], hi, lo);
            size_t o = base + (size_t)(m0 + j) * 64 + (d0 + i);  // [m][k]
            g_vph[o] = hi;
            g_vpl[o] = lo;
        }
}

// ---------------------------------------------------------------------------
// skip_kp partials (wmma bf16x3), 2-stage ping-pong, cp.async ef2, packed STS.
// part[chunk][b][c][k] = sum_{n in chunk} skip[b,n,c]*EF2[n,k]
// ---------------------------------------------------------------------------
__global__ void __launch_bounds__(256) k_skp(const float* __restrict__ skip) {
    int chunk = blockIdx.x, ct = blockIdx.y, b = blockIdx.z;
    __shared__ __nv_bfloat16 ash[2][16][72], asl[2][16][72];   // [stage][n][c]
    __shared__ __nv_bfloat16 bsh[2][16][72], bsl[2][16][72];   // [stage][n][k]
    int t = threadIdx.x, w = t >> 5;

    wmma::fragment<wmma::accumulator, 16, 16, 16, float> acc[2];
    wmma::fill_fragment(acc[0], 0.f);
    wmma::fill_fragment(acc[1], 0.f);
    int c0 = (w >> 1) * 16;
    int kc = (w & 1) * 32;

    int lr = t >> 4, lc4 = (t & 15) * 4;                 // skip loader: 16x64 fp32
    int er = (t & 127) >> 3, ek8 = (t & 7) * 8;          // ef2 cp.async: hi (t<128) / lo
    bool hiload = (t < 128);

    size_t sbase = ((size_t)b * NN + chunk * 1024) * NC + ct * 64 + lc4;
    size_t ebase = (size_t)(chunk * 1024 + er) * 64 + ek8;
    const __nv_bfloat16* esrc = hiload ? g_ef2h : g_ef2l;

    // prologue: stage 0
    cp_async16(hiload ? &bsh[0][er][ek8] : &bsl[0][er][ek8], &esrc[ebase]);
    cp_commit();
    float4 v = *(const float4*)&skip[sbase + (size_t)lr * NC];
    {
        __nv_bfloat16 hx, lx, hy, ly, hz, lz, hw, lw;
        split2(v.x, hx, lx); split2(v.y, hy, ly);
        split2(v.z, hz, lz); split2(v.w, hw, lw);
        *(uint2*)&ash[0][lr][lc4] = make_uint2(pack_bf16(hx, hy), pack_bf16(hz, hw));
        *(uint2*)&asl[0][lr][lc4] = make_uint2(pack_bf16(lx, ly), pack_bf16(lz, lw));
    }
    cp_wait0();
    __syncthreads();

    for (int ns = 0; ns < 64; ns++) {
        int cur = ns & 1, nxt = cur ^ 1;
        // issue next stage loads early (overlap with MMA)
        if (ns < 63) {
            cp_async16(hiload ? &bsh[nxt][er][ek8] : &bsl[nxt][er][ek8],
                       &esrc[ebase + (size_t)(ns + 1) * 16 * 64]);
            cp_commit();
            v = *(const float4*)&skip[sbase + (size_t)((ns + 1) * 16 + lr) * NC];
        }

        wmma::fragment<wmma::matrix_a, 16, 16, 16, __nv_bfloat16, wmma::col_major> ah, al;
        wmma::load_matrix_sync(ah, &ash[cur][0][c0], 72);
        wmma::load_matrix_sync(al, &asl[cur][0][c0], 72);
        #pragma unroll
        for (int kt = 0; kt < 2; kt++) {
            wmma::fragment<wmma::matrix_b, 16, 16, 16, __nv_bfloat16, wmma::row_major> bh, bl;
            wmma::load_matrix_sync(bh, &bsh[cur][0][kc + kt * 16], 72);
            wmma::load_matrix_sync(bl, &bsl[cur][0][kc + kt * 16], 72);
            wmma::mma_sync(acc[kt], ah, bh, acc[kt]);
            wmma::mma_sync(acc[kt], ah, bl, acc[kt]);
            wmma::mma_sync(acc[kt], al, bh, acc[kt]);
        }

        if (ns < 63) {
            __nv_bfloat16 hx, lx, hy, ly, hz, lz, hw, lw;
            split2(v.x, hx, lx); split2(v.y, hy, ly);
            split2(v.z, hz, lz); split2(v.w, hw, lw);
            *(uint2*)&ash[nxt][lr][lc4] = make_uint2(pack_bf16(hx, hy), pack_bf16(hz, hw));
            *(uint2*)&asl[nxt][lr][lc4] = make_uint2(pack_bf16(lx, ly), pack_bf16(lz, lw));
        }
        cp_wait0();
        __syncthreads();
    }
    float* p = g_part + (((size_t)chunk * NB + b) * NC + ct * 64 + c0) * 64 + kc;
    wmma::store_matrix_sync(p, acc[0], 64, wmma::mem_row_major);
    wmma::store_matrix_sync(p + 16, acc[1], 64, wmma::mem_row_major);
}

// ---------------------------------------------------------------------------
// Reduce partials (fixed order), split + TRANSPOSE into g_skp[b][h][k][d]
// ---------------------------------------------------------------------------
__global__ void k_reduce() {
    int i = blockIdx.x * 256 + threadIdx.x;      // over NB*NC*NK = 262144
    float s = 0.f;
    #pragma unroll
    for (int c = 0; c < NCHUNK; c++) s += g_part[(size_t)c * (NB * NC * NK) + i];
    int b = i >> 14, rem = i & 16383, c = rem >> 6, k = rem & 63;
    int h = c >> 6, d = c & 63;
    size_t o = (((size_t)(b * NH + h) * 64 + k) * 64) + d;
    split2(s, g_skph[o], g_skpl[o]);
}

// ---------------------------------------------------------------------------
// Fused attention: q A-fragments direct from global, B via ldmatrix,
// register softmax + P-in-registers. 4 row-tiles (512 rows) per block.
// ---------------------------------------------------------------------------
__global__ void __launch_bounds__(256) k_attn(
    const float* __restrict__ outq, const float* __restrict__ temp,
    float* __restrict__ x)
{
    extern __shared__ char smbuf[];
    __nv_bfloat16* sph = (__nv_bfloat16*)smbuf;          // 64x72  skpT [k][d]
    __nv_bfloat16* spl = sph + 64 * 72;
    __nv_bfloat16* vph = spl + 64 * 72;                  // 64x72  vpT  [m][k]
    __nv_bfloat16* vpl = vph + 64 * 72;
    float* outb = (float*)(vpl + 64 * 72);               // 128x72 out staging

    int nt = blockIdx.x, h = blockIdx.y, b = blockIdx.z;
    int t = threadIdx.x, w = t >> 5, lane = t & 31;
    int gid = lane >> 2, tid = lane & 3;
    int r0 = w * 16;

    int brow = (lane & 7) + ((lane >> 4) << 3);
    int bcol8 = ((lane >> 3) & 1) * 8;

    {
        size_t base = (size_t)(b * NH + h) * 4096;
        for (int i = t; i < 512; i += 256) {
            int r = i >> 3, k8 = (i & 7) * 8;
            *(uint4*)&sph[r * 72 + k8] = *(const uint4*)&g_skph[base + r * 64 + k8];
            *(uint4*)&spl[r * 72 + k8] = *(const uint4*)&g_skpl[base + r * 64 + k8];
            *(uint4*)&vph[r * 72 + k8] = *(const uint4*)&g_vph[base + r * 64 + k8];
            *(uint4*)&vpl[r * 72 + k8] = *(const uint4*)&g_vpl[base + r * 64 + k8];
        }
    }
    float tempv = temp[h];
    __syncthreads();

    #pragma unroll 1
    for (int tile = 0; tile < 4; tile++) {
        int rowbase = nt * 512 + tile * 128 + r0 + gid;
        const float* qr0 = outq + ((size_t)b * NN + rowbase) * NC + h * 64;
        const float* qr8 = qr0 + 8 * NC;

        // ---- logits ----
        float acc[8][4];
        #pragma unroll
        for (int kb = 0; kb < 8; kb++)
            #pragma unroll
            for (int i = 0; i < 4; i++) acc[kb][i] = 0.f;

        #pragma unroll
        for (int dt = 0; dt < 4; dt++) {
            float2 v00 = *(const float2*)&qr0[dt * 16 + 2 * tid];
            float2 v10 = *(const float2*)&qr8[dt * 16 + 2 * tid];
            float2 v01 = *(const float2*)&qr0[dt * 16 + 2 * tid + 8];
            float2 v11 = *(const float2*)&qr8[dt * 16 + 2 * tid + 8];
            unsigned ah[4], al[4];
            {
                __nv_bfloat16 ha, la, hb, lb;
                split2(v00.x, ha, la); split2(v00.y, hb, lb);
                ah[0] = pack_bf16(ha, hb); al[0] = pack_bf16(la, lb);
                split2(v10.x, ha, la); split2(v10.y, hb, lb);
                ah[1] = pack_bf16(ha, hb); al[1] = pack_bf16(la, lb);
                split2(v01.x, ha, la); split2(v01.y, hb, lb);
                ah[2] = pack_bf16(ha, hb); al[2] = pack_bf16(la, lb);
                split2(v11.x, ha, la); split2(v11.y, hb, lb);
                ah[3] = pack_bf16(ha, hb); al[3] = pack_bf16(la, lb);
            }
            #pragma unroll
            for (int p = 0; p < 4; p++) {
                unsigned bh[4], bl[4];
                ldsm_x4(bh, &sph[(p * 16 + brow) * 72 + dt * 16 + bcol8]);
                ldsm_x4(bl, &spl[(p * 16 + brow) * 72 + dt * 16 + bcol8]);
                mma16816(acc[2 * p],     ah, bh);
                mma16816(acc[2 * p],     ah, bl);
                mma16816(acc[2 * p],     al, bh);
                mma16816(acc[2 * p + 1], ah, bh + 2);
                mma16816(acc[2 * p + 1], ah, bl + 2);
                mma16816(acc[2 * p + 1], al, bh + 2);
            }
        }

        // ---- softmax in registers ----
        #pragma unroll
        for (int kb = 0; kb < 8; kb++)
            #pragma unroll
            for (int i = 0; i < 4; i++) acc[kb][i] *= tempv;

        float mx0 = -1e30f, mx1 = -1e30f;
        #pragma unroll
        for (int kb = 0; kb < 8; kb++) {
            mx0 = fmaxf(mx0, fmaxf(acc[kb][0], acc[kb][1]));
            mx1 = fmaxf(mx1, fmaxf(acc[kb][2], acc[kb][3]));
        }
        mx0 = fmaxf(mx0, __shfl_xor_sync(0xffffffffu, mx0, 1));
        mx0 = fmaxf(mx0, __shfl_xor_sync(0xffffffffu, mx0, 2));
        mx1 = fmaxf(mx1, __shfl_xor_sync(0xffffffffu, mx1, 1));
        mx1 = fmaxf(mx1, __shfl_xor_sync(0xffffffffu, mx1, 2));

        float sum0 = 0.f, sum1 = 0.f;
        #pragma unroll
        for (int kb = 0; kb < 8; kb++) {
            acc[kb][0] = __expf(acc[kb][0] - mx0);
            acc[kb][1] = __expf(acc[kb][1] - mx0);
            acc[kb][2] = __expf(acc[kb][2] - mx1);
            acc[kb][3] = __expf(acc[kb][3] - mx1);
            sum0 += acc[kb][0] + acc[kb][1];
            sum1 += acc[kb][2] + acc[kb][3];
        }
        sum0 += __shfl_xor_sync(0xffffffffu, sum0, 1);
        sum0 += __shfl_xor_sync(0xffffffffu, sum0, 2);
        sum1 += __shfl_xor_sync(0xffffffffu, sum1, 1);
        sum1 += __shfl_xor_sync(0xffffffffu, sum1, 2);
        float inv0 = 1.f / sum0, inv1 = 1.f / sum1;

        // ---- pack P into bf16x3 A-fragments ----
        unsigned pah[4][4], pal[4][4];
        #pragma unroll
        for (int kt = 0; kt < 4; kt++) {
            #pragma unroll
            for (int half = 0; half < 2; half++) {
                int kb = 2 * kt + half;
                float p0 = acc[kb][0] * inv0, p1 = acc[kb][1] * inv0;
                float p2 = acc[kb][2] * inv1, p3 = acc[kb][3] * inv1;
                __nv_bfloat16 h0, l0, h1, l1, h2, l2, h3, l3;
                split2(p0, h0, l0); split2(p1, h1, l1);
                split2(p2, h2, l2); split2(p3, h3, l3);
                pah[kt][half * 2]     = pack_bf16(h0, h1);
                pah[kt][half * 2 + 1] = pack_bf16(h2, h3);
                pal[kt][half * 2]     = pack_bf16(l0, l1);
                pal[kt][half * 2 + 1] = pack_bf16(l2, l3);
            }
        }

        // ---- values ----
        float acc2[8][4];
        #pragma unroll
        for (int mb = 0; mb < 8; mb++)
            #pragma unroll
            for (int i = 0; i < 4; i++) acc2[mb][i] = 0.f;

        #pragma unroll
        for (int kt = 0; kt < 4; kt++) {
            #pragma unroll
            for (int p = 0; p < 4; p++) {
                unsigned bh[4], bl[4];
                ldsm_x4(bh, &vph[(p * 16 + brow) * 72 + kt * 16 + bcol8]);
                ldsm_x4(bl, &vpl[(p * 16 + brow) * 72 + kt * 16 + bcol8]);
                mma16816(acc2[2 * p],     pah[kt], bh);
                mma16816(acc2[2 * p],     pah[kt], bl);
                mma16816(acc2[2 * p],     pal[kt], bh);
                mma16816(acc2[2 * p + 1], pah[kt], bh + 2);
                mma16816(acc2[2 * p + 1], pah[kt], bl + 2);
                mma16816(acc2[2 * p + 1], pal[kt], bh + 2);
            }
        }

        // stage output in smem
        #pragma unroll
        for (int mb = 0; mb < 8; mb++) {
            int ob = (r0 + gid) * 72 + mb * 8 + 2 * tid;
            *(float2*)&outb[ob]          = make_float2(acc2[mb][0], acc2[mb][1]);
            *(float2*)&outb[ob + 8 * 72] = make_float2(acc2[mb][2], acc2[mb][3]);
        }
        __syncthreads();

        // permuted writeback: x[b, m*(H*N) + h*N + n], coalesced over n
        {
            int m = t >> 2, rq = (t & 3) * 32;
            float* od = x + (size_t)b * (NN * NC) + (size_t)m * (NH * NN)
                          + (size_t)h * NN + nt * 512 + tile * 128;
            #pragma unroll
            for (int r = rq; r < rq + 32; r += 4) {
                float4 o;
                o.x = outb[(r + 0) * 72 + m];
                o.y = outb[(r + 1) * 72 + m];
                o.z = outb[(r + 2) * 72 + m];
                o.w = outb[(r + 3) * 72 + m];
                *(float4*)&od[r] = o;
            }
        }
        __syncthreads();   // protect outb reuse by next tile
    }
}

// ---------------------------------------------------------------------------
extern "C" void kernel_launch(void* const* d_in, const int* in_sizes, int n_in,
                              void* d_out, int out_size) {
    const float* skip = (const float*)d_in[0];
    const float* outq = (const float*)d_in[1];
    const float* gf   = (const float*)d_in[2];
    const float* ef1  = (const float*)d_in[3];
    const float* ef2  = (const float*)d_in[4];
    const float* temp = (const float*)d_in[5];
    float* x = (float*)d_out;

    cudaFuncSetAttribute(k_attn, cudaFuncAttributeMaxDynamicSharedMemorySize, 73728);

    k_prep_ef2<<<(NN * NK) / 256, 256>>>(ef2);
    k_gvp<<<NB * NH, 256>>>(gf, ef1);
    k_skp<<<dim3(NCHUNK, 4, NB), 256>>>(skip);
    k_reduce<<<(NB * NC * NK) / 256, 256>>>();
    k_attn<<<dim3(NN / 512, NH, NB), 256, 73728>>>(outq, temp, x);
}

// round 7
// speedup vs baseline: 1.6546x; 1.0407x over previous
#include <cuda_runtime.h>
#include <cuda_bf16.h>
#include <mma.h>
#include <math.h>

using namespace nvcuda;

#define NB 16
#define NN 8192
#define NC 256
#define NH 4
#define NK 64
#define NCHUNK 8

// Scratch (__device__ globals; no allocations allowed)
static __device__ float g_part[NCHUNK * NB * NC * NK];          // partials
static __device__ __nv_bfloat16 g_ef2h[NN * NK], g_ef2l[NN * NK];           // [n][k]
static __device__ __nv_bfloat16 g_skph[NB * NC * NK], g_skpl[NB * NC * NK]; // [b][h][k][d]
static __device__ __nv_bfloat16 g_vph[NB * NH * 64 * 64], g_vpl[NB * NH * 64 * 64]; // [b][h][m][k]

__device__ __forceinline__ void split2(float v, __nv_bfloat16& hi, __nv_bfloat16& lo) {
    hi = __float2bfloat16_rn(v);
    lo = __float2bfloat16_rn(v - __bfloat162float(hi));
}

// mma.sync m16n8k16 row.col bf16 -> f32, D += A*B
__device__ __forceinline__ void mma16816(float* c, const unsigned* a, const unsigned* b) {
    asm volatile(
        "mma.sync.aligned.m16n8k16.row.col.f32.bf16.bf16.f32 "
        "{%0,%1,%2,%3}, {%4,%5,%6,%7}, {%8,%9}, {%0,%1,%2,%3};"
        : "+f"(c[0]), "+f"(c[1]), "+f"(c[2]), "+f"(c[3])
        : "r"(a[0]), "r"(a[1]), "r"(a[2]), "r"(a[3]), "r"(b[0]), "r"(b[1]));
}

__device__ __forceinline__ void ldsm_x4(unsigned* r, const void* p) {
    unsigned a = (unsigned)__cvta_generic_to_shared(p);
    asm volatile("ldmatrix.sync.aligned.m8n8.x4.shared.b16 {%0,%1,%2,%3}, [%4];"
        : "=r"(r[0]), "=r"(r[1]), "=r"(r[2]), "=r"(r[3]) : "r"(a));
}

__device__ __forceinline__ unsigned pack_bf16(__nv_bfloat16 lo, __nv_bfloat16 hi) {
    __nv_bfloat162 p = __halves2bfloat162(lo, hi);   // .x = low half
    return *(unsigned*)&p;
}

__device__ __forceinline__ void cp_async16(void* smem, const void* gmem) {
    unsigned s = (unsigned)__cvta_generic_to_shared(smem);
    asm volatile("cp.async.cg.shared.global [%0], [%1], 16;" :: "r"(s), "l"(gmem));
}
__device__ __forceinline__ void cp_commit() { asm volatile("cp.async.commit_group;"); }
__device__ __forceinline__ void cp_wait0()  { asm volatile("cp.async.wait_group 0;" ::: "memory"); }

// ---------------------------------------------------------------------------
__global__ void k_prep_ef2(const float* __restrict__ ef2) {
    int i = blockIdx.x * 256 + threadIdx.x;
    split2(ef2[i], g_ef2h[i], g_ef2l[i]);
}

// global_vp (fp32, tiny), fused split + transpose epilogue:
// g_vph[bh][m][k=d1] = split(sum_n1 gf[b,n1,h*64+d1]*EF1[n1,m])
__global__ void k_gvp(const float* __restrict__ gf, const float* __restrict__ ef1) {
    int bh = blockIdx.x, b = bh >> 2, h = bh & 3;
    __shared__ float gs[64][64];
    __shared__ float es[64][64];
    int t = threadIdx.x;
    for (int i = t; i < 4096; i += 256) {
        int r = i >> 6, c = i & 63;
        gs[r][c] = gf[(b * 64 + r) * 256 + h * 64 + c];
        es[r][c] = ef1[i];
    }
    __syncthreads();
    int d0 = (t >> 4) << 2, m0 = (t & 15) << 2;
    float acc[4][4] = {};
    for (int n1 = 0; n1 < 64; n1++) {
        float4 a = *(const float4*)&gs[n1][d0];
        float4 v = *(const float4*)&es[n1][m0];
        float av[4] = {a.x, a.y, a.z, a.w};
        float bv[4] = {v.x, v.y, v.z, v.w};
        #pragma unroll
        for (int i = 0; i < 4; i++)
            #pragma unroll
            for (int j = 0; j < 4; j++)
                acc[i][j] += av[i] * bv[j];
    }
    size_t base = (size_t)bh * 4096;
    #pragma unroll
    for (int i = 0; i < 4; i++)
        #pragma unroll
        for (int j = 0; j < 4; j++) {
            __nv_bfloat16 hi, lo;
            split2(acc[i][j], hi, lo);
            size_t o = base + (size_t)(m0 + j) * 64 + (d0 + i);  // [m][k]
            g_vph[o] = hi;
            g_vpl[o] = lo;
        }
}

// ---------------------------------------------------------------------------
// skip_kp partials (wmma bf16x3).
// 64-row SUPERSTEPS: one barrier per 64 rows (16 barriers total), 16 KB of
// skip loads in flight per CTA, MMA block (~4x16-row sub-steps) covers the
// DRAM latency of the next superstep's loads. 2-stage ping-pong smem (72 KB).
// part[chunk][b][c][k] = sum_{n in chunk} skip[b,n,c]*EF2[n,k]
// ---------------------------------------------------------------------------
__global__ void __launch_bounds__(256) k_skp(const float* __restrict__ skip) {
    extern __shared__ char sm[];
    __nv_bfloat16* ash = (__nv_bfloat16*)sm;            // [2][64][72]
    __nv_bfloat16* asl = ash + 2 * 64 * 72;
    __nv_bfloat16* bsh = asl + 2 * 64 * 72;
    __nv_bfloat16* bsl = bsh + 2 * 64 * 72;
    const int SST = 64 * 72;                             // stage stride

    int chunk = blockIdx.x, ct = blockIdx.y, b = blockIdx.z;
    int t = threadIdx.x, w = t >> 5;

    wmma::fragment<wmma::accumulator, 16, 16, 16, float> acc[2];
    wmma::fill_fragment(acc[0], 0.f);
    wmma::fill_fragment(acc[1], 0.f);
    int c0 = (w >> 1) * 16;
    int kc = (w & 1) * 32;

    int lr = t >> 4, lc4 = (t & 15) * 4;                 // skip loader base row/col
    int er = (t & 127) >> 3, ek8 = (t & 7) * 8;          // ef2 cp.async base
    bool hiload = (t < 128);

    size_t sbase = ((size_t)b * NN + chunk * 1024) * NC + ct * 64 + lc4;
    size_t ebase = (size_t)(chunk * 1024 + er) * 64 + ek8;
    const __nv_bfloat16* esrc = hiload ? g_ef2h : g_ef2l;
    __nv_bfloat16* bdst = hiload ? bsh : bsl;

    float4 v[4];

    // prologue: superstep 0 into stage 0
    #pragma unroll
    for (int j = 0; j < 4; j++) {
        cp_async16(&bdst[(j * 16 + er) * 72 + ek8], &esrc[ebase + (size_t)(j * 16) * 64]);
        v[j] = *(const float4*)&skip[sbase + (size_t)(j * 16 + lr) * NC];
    }
    cp_commit();
    #pragma unroll
    for (int j = 0; j < 4; j++) {
        __nv_bfloat16 hx, lx, hy, ly, hz, lz, hw, lw;
        split2(v[j].x, hx, lx); split2(v[j].y, hy, ly);
        split2(v[j].z, hz, lz); split2(v[j].w, hw, lw);
        int row = j * 16 + lr;
        *(uint2*)&ash[row * 72 + lc4] = make_uint2(pack_bf16(hx, hy), pack_bf16(hz, hw));
        *(uint2*)&asl[row * 72 + lc4] = make_uint2(pack_bf16(lx, ly), pack_bf16(lz, lw));
    }
    cp_wait0();
    __syncthreads();

    for (int ss = 0; ss < 16; ss++) {
        int cur = ss & 1, nxt = cur ^ 1;

        // issue next superstep's loads early (overlap with the MMA block)
        if (ss < 15) {
            size_t srow = sbase + (size_t)((ss + 1) * 64) * NC;
            size_t eoff = ebase + (size_t)((ss + 1) * 64) * 64;
            #pragma unroll
            for (int j = 0; j < 4; j++) {
                cp_async16(&bdst[(nxt * 64 + j * 16 + er) * 72 + ek8],
                           &esrc[eoff + (size_t)(j * 16) * 64]);
                v[j] = *(const float4*)&skip[srow + (size_t)(j * 16 + lr) * NC];
            }
            cp_commit();
        }

        // MMA block: 4 sub-steps of 16 rows
        #pragma unroll
        for (int sub = 0; sub < 4; sub++) {
            const __nv_bfloat16* ap = &ash[(cur * 64 + sub * 16) * 72 + c0];
            const __nv_bfloat16* alp = &asl[(cur * 64 + sub * 16) * 72 + c0];
            wmma::fragment<wmma::matrix_a, 16, 16, 16, __nv_bfloat16, wmma::col_major> ah, al;
            wmma::load_matrix_sync(ah, ap, 72);
            wmma::load_matrix_sync(al, alp, 72);
            #pragma unroll
            for (int kt = 0; kt < 2; kt++) {
                wmma::fragment<wmma::matrix_b, 16, 16, 16, __nv_bfloat16, wmma::row_major> bh, bl;
                wmma::load_matrix_sync(bh, &bsh[(cur * 64 + sub * 16) * 72 + kc + kt * 16], 72);
                wmma::load_matrix_sync(bl, &bsl[(cur * 64 + sub * 16) * 72 + kc + kt * 16], 72);
                wmma::mma_sync(acc[kt], ah, bh, acc[kt]);
                wmma::mma_sync(acc[kt], ah, bl, acc[kt]);
                wmma::mma_sync(acc[kt], al, bh, acc[kt]);
            }
        }

        if (ss < 15) {
            #pragma unroll
            for (int j = 0; j < 4; j++) {
                __nv_bfloat16 hx, lx, hy, ly, hz, lz, hw, lw;
                split2(v[j].x, hx, lx); split2(v[j].y, hy, ly);
                split2(v[j].z, hz, lz); split2(v[j].w, hw, lw);
                int row = nxt * 64 + j * 16 + lr;
                *(uint2*)&ash[row * 72 + lc4] = make_uint2(pack_bf16(hx, hy), pack_bf16(hz, hw));
                *(uint2*)&asl[row * 72 + lc4] = make_uint2(pack_bf16(lx, ly), pack_bf16(lz, lw));
            }
        }
        cp_wait0();
        __syncthreads();
    }

    float* p = g_part + (((size_t)chunk * NB + b) * NC + ct * 64 + c0) * 64 + kc;
    wmma::store_matrix_sync(p, acc[0], 64, wmma::mem_row_major);
    wmma::store_matrix_sync(p + 16, acc[1], 64, wmma::mem_row_major);
}

// ---------------------------------------------------------------------------
// Reduce partials (fixed order), split + TRANSPOSE into g_skp[b][h][k][d]
// ---------------------------------------------------------------------------
__global__ void k_reduce() {
    int i = blockIdx.x * 256 + threadIdx.x;      // over NB*NC*NK = 262144
    float s = 0.f;
    #pragma unroll
    for (int c = 0; c < NCHUNK; c++) s += g_part[(size_t)c * (NB * NC * NK) + i];
    int b = i >> 14, rem = i & 16383, c = rem >> 6, k = rem & 63;
    int h = c >> 6, d = c & 63;
    size_t o = (((size_t)(b * NH + h) * 64 + k) * 64) + d;
    split2(s, g_skph[o], g_skpl[o]);
}

// ---------------------------------------------------------------------------
// Fused attention: q A-fragments direct from global, B via ldmatrix,
// register softmax + P-in-registers. 4 row-tiles (512 rows) per block.
// ---------------------------------------------------------------------------
__global__ void __launch_bounds__(256) k_attn(
    const float* __restrict__ outq, const float* __restrict__ temp,
    float* __restrict__ x)
{
    extern __shared__ char smbuf[];
    __nv_bfloat16* sph = (__nv_bfloat16*)smbuf;          // 64x72  skpT [k][d]
    __nv_bfloat16* spl = sph + 64 * 72;
    __nv_bfloat16* vph = spl + 64 * 72;                  // 64x72  vpT  [m][k]
    __nv_bfloat16* vpl = vph + 64 * 72;
    float* outb = (float*)(vpl + 64 * 72);               // 128x72 out staging

    int nt = blockIdx.x, h = blockIdx.y, b = blockIdx.z;
    int t = threadIdx.x, w = t >> 5, lane = t & 31;
    int gid = lane >> 2, tid = lane & 3;
    int r0 = w * 16;

    int brow = (lane & 7) + ((lane >> 4) << 3);
    int bcol8 = ((lane >> 3) & 1) * 8;

    {
        size_t base = (size_t)(b * NH + h) * 4096;
        for (int i = t; i < 512; i += 256) {
            int r = i >> 3, k8 = (i & 7) * 8;
            *(uint4*)&sph[r * 72 + k8] = *(const uint4*)&g_skph[base + r * 64 + k8];
            *(uint4*)&spl[r * 72 + k8] = *(const uint4*)&g_skpl[base + r * 64 + k8];
            *(uint4*)&vph[r * 72 + k8] = *(const uint4*)&g_vph[base + r * 64 + k8];
            *(uint4*)&vpl[r * 72 + k8] = *(const uint4*)&g_vpl[base + r * 64 + k8];
        }
    }
    float tempv = temp[h];
    __syncthreads();

    #pragma unroll 1
    for (int tile = 0; tile < 4; tile++) {
        int rowbase = nt * 512 + tile * 128 + r0 + gid;
        const float* qr0 = outq + ((size_t)b * NN + rowbase) * NC + h * 64;
        const float* qr8 = qr0 + 8 * NC;

        // ---- logits ----
        float acc[8][4];
        #pragma unroll
        for (int kb = 0; kb < 8; kb++)
            #pragma unroll
            for (int i = 0; i < 4; i++) acc[kb][i] = 0.f;

        #pragma unroll
        for (int dt = 0; dt < 4; dt++) {
            float2 v00 = *(const float2*)&qr0[dt * 16 + 2 * tid];
            float2 v10 = *(const float2*)&qr8[dt * 16 + 2 * tid];
            float2 v01 = *(const float2*)&qr0[dt * 16 + 2 * tid + 8];
            float2 v11 = *(const float2*)&qr8[dt * 16 + 2 * tid + 8];
            unsigned ah[4], al[4];
            {
                __nv_bfloat16 ha, la, hb, lb;
                split2(v00.x, ha, la); split2(v00.y, hb, lb);
                ah[0] = pack_bf16(ha, hb); al[0] = pack_bf16(la, lb);
                split2(v10.x, ha, la); split2(v10.y, hb, lb);
                ah[1] = pack_bf16(ha, hb); al[1] = pack_bf16(la, lb);
                split2(v01.x, ha, la); split2(v01.y, hb, lb);
                ah[2] = pack_bf16(ha, hb); al[2] = pack_bf16(la, lb);
                split2(v11.x, ha, la); split2(v11.y, hb, lb);
                ah[3] = pack_bf16(ha, hb); al[3] = pack_bf16(la, lb);
            }
            #pragma unroll
            for (int p = 0; p < 4; p++) {
                unsigned bh[4], bl[4];
                ldsm_x4(bh, &sph[(p * 16 + brow) * 72 + dt * 16 + bcol8]);
                ldsm_x4(bl, &spl[(p * 16 + brow) * 72 + dt * 16 + bcol8]);
                mma16816(acc[2 * p],     ah, bh);
                mma16816(acc[2 * p],     ah, bl);
                mma16816(acc[2 * p],     al, bh);
                mma16816(acc[2 * p + 1], ah, bh + 2);
                mma16816(acc[2 * p + 1], ah, bl + 2);
                mma16816(acc[2 * p + 1], al, bh + 2);
            }
        }

        // ---- softmax in registers ----
        #pragma unroll
        for (int kb = 0; kb < 8; kb++)
            #pragma unroll
            for (int i = 0; i < 4; i++) acc[kb][i] *= tempv;

        float mx0 = -1e30f, mx1 = -1e30f;
        #pragma unroll
        for (int kb = 0; kb < 8; kb++) {
            mx0 = fmaxf(mx0, fmaxf(acc[kb][0], acc[kb][1]));
            mx1 = fmaxf(mx1, fmaxf(acc[kb][2], acc[kb][3]));
        }
        mx0 = fmaxf(mx0, __shfl_xor_sync(0xffffffffu, mx0, 1));
        mx0 = fmaxf(mx0, __shfl_xor_sync(0xffffffffu, mx0, 2));
        mx1 = fmaxf(mx1, __shfl_xor_sync(0xffffffffu, mx1, 1));
        mx1 = fmaxf(mx1, __shfl_xor_sync(0xffffffffu, mx1, 2));

        float sum0 = 0.f, sum1 = 0.f;
        #pragma unroll
        for (int kb = 0; kb < 8; kb++) {
            acc[kb][0] = __expf(acc[kb][0] - mx0);
            acc[kb][1] = __expf(acc[kb][1] - mx0);
            acc[kb][2] = __expf(acc[kb][2] - mx1);
            acc[kb][3] = __expf(acc[kb][3] - mx1);
            sum0 += acc[kb][0] + acc[kb][1];
            sum1 += acc[kb][2] + acc[kb][3];
        }
        sum0 += __shfl_xor_sync(0xffffffffu, sum0, 1);
        sum0 += __shfl_xor_sync(0xffffffffu, sum0, 2);
        sum1 += __shfl_xor_sync(0xffffffffu, sum1, 1);
        sum1 += __shfl_xor_sync(0xffffffffu, sum1, 2);
        float inv0 = 1.f / sum0, inv1 = 1.f / sum1;

        // ---- pack P into bf16x3 A-fragments ----
        unsigned pah[4][4], pal[4][4];
        #pragma unroll
        for (int kt = 0; kt < 4; kt++) {
            #pragma unroll
            for (int half = 0; half < 2; half++) {
                int kb = 2 * kt + half;
                float p0 = acc[kb][0] * inv0, p1 = acc[kb][1] * inv0;
                float p2 = acc[kb][2] * inv1, p3 = acc[kb][3] * inv1;
                __nv_bfloat16 h0, l0, h1, l1, h2, l2, h3, l3;
                split2(p0, h0, l0); split2(p1, h1, l1);
                split2(p2, h2, l2); split2(p3, h3, l3);
                pah[kt][half * 2]     = pack_bf16(h0, h1);
                pah[kt][half * 2 + 1] = pack_bf16(h2, h3);
                pal[kt][half * 2]     = pack_bf16(l0, l1);
                pal[kt][half * 2 + 1] = pack_bf16(l2, l3);
            }
        }

        // ---- values ----
        float acc2[8][4];
        #pragma unroll
        for (int mb = 0; mb < 8; mb++)
            #pragma unroll
            for (int i = 0; i < 4; i++) acc2[mb][i] = 0.f;

        #pragma unroll
        for (int kt = 0; kt < 4; kt++) {
            #pragma unroll
            for (int p = 0; p < 4; p++) {
                unsigned bh[4], bl[4];
                ldsm_x4(bh, &vph[(p * 16 + brow) * 72 + kt * 16 + bcol8]);
                ldsm_x4(bl, &vpl[(p * 16 + brow) * 72 + kt * 16 + bcol8]);
                mma16816(acc2[2 * p],     pah[kt], bh);
                mma16816(acc2[2 * p],     pah[kt], bl);
                mma16816(acc2[2 * p],     pal[kt], bh);
                mma16816(acc2[2 * p + 1], pah[kt], bh + 2);
                mma16816(acc2[2 * p + 1], pah[kt], bl + 2);
                mma16816(acc2[2 * p + 1], pal[kt], bh + 2);
            }
        }

        // stage output in smem
        #pragma unroll
        for (int mb = 0; mb < 8; mb++) {
            int ob = (r0 + gid) * 72 + mb * 8 + 2 * tid;
            *(float2*)&outb[ob]          = make_float2(acc2[mb][0], acc2[mb][1]);
            *(float2*)&outb[ob + 8 * 72] = make_float2(acc2[mb][2], acc2[mb][3]);
        }
        __syncthreads();

        // permuted writeback: x[b, m*(H*N) + h*N + n], coalesced over n
        {
            int m = t >> 2, rq = (t & 3) * 32;
            float* od = x + (size_t)b * (NN * NC) + (size_t)m * (NH * NN)
                          + (size_t)h * NN + nt * 512 + tile * 128;
            #pragma unroll
            for (int r = rq; r < rq + 32; r += 4) {
                float4 o;
                o.x = outb[(r + 0) * 72 + m];
                o.y = outb[(r + 1) * 72 + m];
                o.z = outb[(r + 2) * 72 + m];
                o.w = outb[(r + 3) * 72 + m];
                *(float4*)&od[r] = o;
            }
        }
        __syncthreads();   // protect outb reuse by next tile
    }
}

// ---------------------------------------------------------------------------
extern "C" void kernel_launch(void* const* d_in, const int* in_sizes, int n_in,
                              void* d_out, int out_size) {
    const float* skip = (const float*)d_in[0];
    const float* outq = (const float*)d_in[1];
    const float* gf   = (const float*)d_in[2];
    const float* ef1  = (const float*)d_in[3];
    const float* ef2  = (const float*)d_in[4];
    const float* temp = (const float*)d_in[5];
    float* x = (float*)d_out;

    cudaFuncSetAttribute(k_attn, cudaFuncAttributeMaxDynamicSharedMemorySize, 73728);
    cudaFuncSetAttribute(k_skp,  cudaFuncAttributeMaxDynamicSharedMemorySize, 73728);

    k_prep_ef2<<<(NN * NK) / 256, 256>>>(ef2);
    k_gvp<<<NB * NH, 256>>>(gf, ef1);
    k_skp<<<dim3(NCHUNK, 4, NB), 256, 73728>>>(skip);
    k_reduce<<<(NB * NC * NK) / 256, 256>>>();
    k_attn<<<dim3(NN / 512, NH, NB), 256, 73728>>>(outq, temp, x);
}

// round 9
// speedup vs baseline: 1.8778x; 1.1349x over previous
#include <cuda_runtime.h>
#include <cuda_bf16.h>
#include <mma.h>
#include <math.h>

using namespace nvcuda;

#define NB 16
#define NN 8192
#define NC 256
#define NH 4
#define NK 64
#define NCHUNK 8

// Scratch (__device__ globals; no allocations allowed)
static __device__ float g_part[NCHUNK * NB * NC * NK];          // partials
static __device__ __nv_bfloat16 g_ef2h[NN * NK], g_ef2l[NN * NK];           // [n][k]
static __device__ __nv_bfloat16 g_skph[NB * NC * NK], g_skpl[NB * NC * NK]; // [b][h][k][d]
static __device__ __nv_bfloat16 g_vph[NB * NH * 64 * 64], g_vpl[NB * NH * 64 * 64]; // [b][h][m][k]

__device__ __forceinline__ void split2(float v, __nv_bfloat16& hi, __nv_bfloat16& lo) {
    hi = __float2bfloat16_rn(v);
    lo = __float2bfloat16_rn(v - __bfloat162float(hi));
}

// mma.sync m16n8k16 row.col bf16 -> f32, D += A*B
__device__ __forceinline__ void mma16816(float* c, const unsigned* a, const unsigned* b) {
    asm volatile(
        "mma.sync.aligned.m16n8k16.row.col.f32.bf16.bf16.f32 "
        "{%0,%1,%2,%3}, {%4,%5,%6,%7}, {%8,%9}, {%0,%1,%2,%3};"
        : "+f"(c[0]), "+f"(c[1]), "+f"(c[2]), "+f"(c[3])
        : "r"(a[0]), "r"(a[1]), "r"(a[2]), "r"(a[3]), "r"(b[0]), "r"(b[1]));
}

__device__ __forceinline__ void ldsm_x4(unsigned* r, const void* p) {
    unsigned a = (unsigned)__cvta_generic_to_shared(p);
    asm volatile("ldmatrix.sync.aligned.m8n8.x4.shared.b16 {%0,%1,%2,%3}, [%4];"
        : "=r"(r[0]), "=r"(r[1]), "=r"(r[2]), "=r"(r[3]) : "r"(a));
}

__device__ __forceinline__ unsigned pack_bf16(__nv_bfloat16 lo, __nv_bfloat16 hi) {
    __nv_bfloat162 p = __halves2bfloat162(lo, hi);   // .x = low half
    return *(unsigned*)&p;
}

__device__ __forceinline__ void cp_async16(void* smem, const void* gmem) {
    unsigned s = (unsigned)__cvta_generic_to_shared(smem);
    asm volatile("cp.async.cg.shared.global [%0], [%1], 16;" :: "r"(s), "l"(gmem));
}
__device__ __forceinline__ void cp_commit() { asm volatile("cp.async.commit_group;"); }
__device__ __forceinline__ void cp_wait0()  { asm volatile("cp.async.wait_group 0;" ::: "memory"); }

// ---------------------------------------------------------------------------
__global__ void k_prep_ef2(const float* __restrict__ ef2) {
    int i = blockIdx.x * 256 + threadIdx.x;
    split2(ef2[i], g_ef2h[i], g_ef2l[i]);
}

// global_vp (fp32, tiny), fused split + transpose epilogue:
// g_vph[bh][m][k=d1] = split(sum_n1 gf[b,n1,h*64+d1]*EF1[n1,m])
__global__ void k_gvp(const float* __restrict__ gf, const float* __restrict__ ef1) {
    int bh = blockIdx.x, b = bh >> 2, h = bh & 3;
    __shared__ float gs[64][64];
    __shared__ float es[64][64];
    int t = threadIdx.x;
    for (int i = t; i < 4096; i += 256) {
        int r = i >> 6, c = i & 63;
        gs[r][c] = gf[(b * 64 + r) * 256 + h * 64 + c];
        es[r][c] = ef1[i];
    }
    __syncthreads();
    int d0 = (t >> 4) << 2, m0 = (t & 15) << 2;
    float acc[4][4] = {};
    for (int n1 = 0; n1 < 64; n1++) {
        float4 a = *(const float4*)&gs[n1][d0];
        float4 v = *(const float4*)&es[n1][m0];
        float av[4] = {a.x, a.y, a.z, a.w};
        float bv[4] = {v.x, v.y, v.z, v.w};
        #pragma unroll
        for (int i = 0; i < 4; i++)
            #pragma unroll
            for (int j = 0; j < 4; j++)
                acc[i][j] += av[i] * bv[j];
    }
    size_t base = (size_t)bh * 4096;
    #pragma unroll
    for (int i = 0; i < 4; i++)
        #pragma unroll
        for (int j = 0; j < 4; j++) {
            __nv_bfloat16 hi, lo;
            split2(acc[i][j], hi, lo);
            size_t o = base + (size_t)(m0 + j) * 64 + (d0 + i);  // [m][k]
            g_vph[o] = hi;
            g_vpl[o] = lo;
        }
}

// ---------------------------------------------------------------------------
// skip_kp partials (wmma bf16x3).
// 32-row supersteps, 2-stage ping-pong (36.9 KB smem -> occupancy 4,
// all 512 CTAs resident in ONE wave). One barrier per superstep.
// part[chunk][b][c][k] = sum_{n in chunk} skip[b,n,c]*EF2[n,k]
// ---------------------------------------------------------------------------
__global__ void __launch_bounds__(256) k_skp(const float* __restrict__ skip) {
    extern __shared__ char sm[];
    __nv_bfloat16* ash = (__nv_bfloat16*)sm;            // [2][32][72]
    __nv_bfloat16* asl = ash + 2 * 32 * 72;
    __nv_bfloat16* bsh = asl + 2 * 32 * 72;
    __nv_bfloat16* bsl = bsh + 2 * 32 * 72;

    int chunk = blockIdx.x, ct = blockIdx.y, b = blockIdx.z;
    int t = threadIdx.x, w = t >> 5;

    wmma::fragment<wmma::accumulator, 16, 16, 16, float> acc[2];
    wmma::fill_fragment(acc[0], 0.f);
    wmma::fill_fragment(acc[1], 0.f);
    int c0 = (w >> 1) * 16;
    int kc = (w & 1) * 32;

    int lr = t >> 4, lc4 = (t & 15) * 4;                 // skip loader: rows lr, lr+16
    int er = (t & 127) >> 3, ek8 = (t & 7) * 8;          // ef2: rows er, er+16
    bool hiload = (t < 128);

    size_t sbase = ((size_t)b * NN + chunk * 1024) * NC + ct * 64 + lc4;
    size_t ebase = (size_t)(chunk * 1024 + er) * 64 + ek8;
    const __nv_bfloat16* esrc = hiload ? g_ef2h : g_ef2l;
    __nv_bfloat16* bdst = hiload ? bsh : bsl;

    float4 v[2];

    // prologue: superstep 0 into stage 0
    #pragma unroll
    for (int j = 0; j < 2; j++) {
        cp_async16(&bdst[(j * 16 + er) * 72 + ek8], &esrc[ebase + (size_t)(j * 16) * 64]);
        v[j] = *(const float4*)&skip[sbase + (size_t)(j * 16 + lr) * NC];
    }
    cp_commit();
    #pragma unroll
    for (int j = 0; j < 2; j++) {
        __nv_bfloat16 hx, lx, hy, ly, hz, lz, hw, lw;
        split2(v[j].x, hx, lx); split2(v[j].y, hy, ly);
        split2(v[j].z, hz, lz); split2(v[j].w, hw, lw);
        int row = j * 16 + lr;
        *(uint2*)&ash[row * 72 + lc4] = make_uint2(pack_bf16(hx, hy), pack_bf16(hz, hw));
        *(uint2*)&asl[row * 72 + lc4] = make_uint2(pack_bf16(lx, ly), pack_bf16(lz, lw));
    }
    cp_wait0();
    __syncthreads();

    for (int ss = 0; ss < 32; ss++) {
        int cur = ss & 1, nxt = cur ^ 1;

        // issue next superstep's loads early (overlap with the MMA block)
        if (ss < 31) {
            size_t srow = sbase + (size_t)((ss + 1) * 32) * NC;
            size_t eoff = ebase + (size_t)((ss + 1) * 32) * 64;
            #pragma unroll
            for (int j = 0; j < 2; j++) {
                cp_async16(&bdst[(nxt * 32 + j * 16 + er) * 72 + ek8],
                           &esrc[eoff + (size_t)(j * 16) * 64]);
                v[j] = *(const float4*)&skip[srow + (size_t)(j * 16 + lr) * NC];
            }
            cp_commit();
        }

        // MMA block: 2 sub-steps of 16 rows
        #pragma unroll
        for (int sub = 0; sub < 2; sub++) {
            wmma::fragment<wmma::matrix_a, 16, 16, 16, __nv_bfloat16, wmma::col_major> ah, al;
            wmma::load_matrix_sync(ah, &ash[(cur * 32 + sub * 16) * 72 + c0], 72);
            wmma::load_matrix_sync(al, &asl[(cur * 32 + sub * 16) * 72 + c0], 72);
            #pragma unroll
            for (int kt = 0; kt < 2; kt++) {
                wmma::fragment<wmma::matrix_b, 16, 16, 16, __nv_bfloat16, wmma::row_major> bh, bl;
                wmma::load_matrix_sync(bh, &bsh[(cur * 32 + sub * 16) * 72 + kc + kt * 16], 72);
                wmma::load_matrix_sync(bl, &bsl[(cur * 32 + sub * 16) * 72 + kc + kt * 16], 72);
                wmma::mma_sync(acc[kt], ah, bh, acc[kt]);
                wmma::mma_sync(acc[kt], ah, bl, acc[kt]);
                wmma::mma_sync(acc[kt], al, bh, acc[kt]);
            }
        }

        if (ss < 31) {
            #pragma unroll
            for (int j = 0; j < 2; j++) {
                __nv_bfloat16 hx, lx, hy, ly, hz, lz, hw, lw;
                split2(v[j].x, hx, lx); split2(v[j].y, hy, ly);
                split2(v[j].z, hz, lz); split2(v[j].w, hw, lw);
                int row = nxt * 32 + j * 16 + lr;
                *(uint2*)&ash[row * 72 + lc4] = make_uint2(pack_bf16(hx, hy), pack_bf16(hz, hw));
                *(uint2*)&asl[row * 72 + lc4] = make_uint2(pack_bf16(lx, ly), pack_bf16(lz, lw));
            }
        }
        cp_wait0();
        __syncthreads();
    }

    float* p = g_part + (((size_t)chunk * NB + b) * NC + ct * 64 + c0) * 64 + kc;
    wmma::store_matrix_sync(p, acc[0], 64, wmma::mem_row_major);
    wmma::store_matrix_sync(p + 16, acc[1], 64, wmma::mem_row_major);
}

// ---------------------------------------------------------------------------
// Reduce partials (fixed order), split + TRANSPOSE into g_skp[b][h][k][d]
// ---------------------------------------------------------------------------
__global__ void k_reduce() {
    int i = blockIdx.x * 256 + threadIdx.x;      // over NB*NC*NK = 262144
    float s = 0.f;
    #pragma unroll
    for (int c = 0; c < NCHUNK; c++) s += g_part[(size_t)c * (NB * NC * NK) + i];
    int b = i >> 14, rem = i & 16383, c = rem >> 6, k = rem & 63;
    int h = c >> 6, d = c & 63;
    size_t o = (((size_t)(b * NH + h) * 64 + k) * 64) + d;
    split2(s, g_skph[o], g_skpl[o]);
}

// ---------------------------------------------------------------------------
// Fused attention: q A-fragments direct from global, B via ldmatrix,
// register softmax + P-in-registers. 4 row-tiles (512 rows) per block.
// outb stride 74 floats (even -> aligned float2 stores; (74r+m)%32 spreads
// reads across all 32 banks); coalesced 64B quad writes.
// ---------------------------------------------------------------------------
#define OSTR 74

__global__ void __launch_bounds__(256) k_attn(
    const float* __restrict__ outq, const float* __restrict__ temp,
    float* __restrict__ x)
{
    extern __shared__ char smbuf[];
    __nv_bfloat16* sph = (__nv_bfloat16*)smbuf;          // 64x72  skpT [k][d]
    __nv_bfloat16* spl = sph + 64 * 72;
    __nv_bfloat16* vph = spl + 64 * 72;                  // 64x72  vpT  [m][k]
    __nv_bfloat16* vpl = vph + 64 * 72;
    float* outb = (float*)(vpl + 64 * 72);               // 128xOSTR out staging

    int nt = blockIdx.x, h = blockIdx.y, b = blockIdx.z;
    int t = threadIdx.x, w = t >> 5, lane = t & 31;
    int gid = lane >> 2, tid = lane & 3;
    int r0 = w * 16;

    int brow = (lane & 7) + ((lane >> 4) << 3);
    int bcol8 = ((lane >> 3) & 1) * 8;

    {
        size_t base = (size_t)(b * NH + h) * 4096;
        for (int i = t; i < 512; i += 256) {
            int r = i >> 3, k8 = (i & 7) * 8;
            *(uint4*)&sph[r * 72 + k8] = *(const uint4*)&g_skph[base + r * 64 + k8];
            *(uint4*)&spl[r * 72 + k8] = *(const uint4*)&g_skpl[base + r * 64 + k8];
            *(uint4*)&vph[r * 72 + k8] = *(const uint4*)&g_vph[base + r * 64 + k8];
            *(uint4*)&vpl[r * 72 + k8] = *(const uint4*)&g_vpl[base + r * 64 + k8];
        }
    }
    float tempv = temp[h];
    __syncthreads();

    #pragma unroll 1
    for (int tile = 0; tile < 4; tile++) {
        int rowbase = nt * 512 + tile * 128 + r0 + gid;
        const float* qr0 = outq + ((size_t)b * NN + rowbase) * NC + h * 64;
        const float* qr8 = qr0 + 8 * NC;

        // ---- logits ----
        float acc[8][4];
        #pragma unroll
        for (int kb = 0; kb < 8; kb++)
            #pragma unroll
            for (int i = 0; i < 4; i++) acc[kb][i] = 0.f;

        #pragma unroll
        for (int dt = 0; dt < 4; dt++) {
            float2 v00 = *(const float2*)&qr0[dt * 16 + 2 * tid];
            float2 v10 = *(const float2*)&qr8[dt * 16 + 2 * tid];
            float2 v01 = *(const float2*)&qr0[dt * 16 + 2 * tid + 8];
            float2 v11 = *(const float2*)&qr8[dt * 16 + 2 * tid + 8];
            unsigned ah[4], al[4];
            {
                __nv_bfloat16 ha, la, hb, lb;
                split2(v00.x, ha, la); split2(v00.y, hb, lb);
                ah[0] = pack_bf16(ha, hb); al[0] = pack_bf16(la, lb);
                split2(v10.x, ha, la); split2(v10.y, hb, lb);
                ah[1] = pack_bf16(ha, hb); al[1] = pack_bf16(la, lb);
                split2(v01.x, ha, la); split2(v01.y, hb, lb);
                ah[2] = pack_bf16(ha, hb); al[2] = pack_bf16(la, lb);
                split2(v11.x, ha, la); split2(v11.y, hb, lb);
                ah[3] = pack_bf16(ha, hb); al[3] = pack_bf16(la, lb);
            }
            #pragma unroll
            for (int p = 0; p < 4; p++) {
                unsigned bh[4], bl[4];
                ldsm_x4(bh, &sph[(p * 16 + brow) * 72 + dt * 16 + bcol8]);
                ldsm_x4(bl, &spl[(p * 16 + brow) * 72 + dt * 16 + bcol8]);
                mma16816(acc[2 * p],     ah, bh);
                mma16816(acc[2 * p],     ah, bl);
                mma16816(acc[2 * p],     al, bh);
                mma16816(acc[2 * p + 1], ah, bh + 2);
                mma16816(acc[2 * p + 1], ah, bl + 2);
                mma16816(acc[2 * p + 1], al, bh + 2);
            }
        }

        // ---- softmax in registers ----
        #pragma unroll
        for (int kb = 0; kb < 8; kb++)
            #pragma unroll
            for (int i = 0; i < 4; i++) acc[kb][i] *= tempv;

        float mx0 = -1e30f, mx1 = -1e30f;
        #pragma unroll
        for (int kb = 0; kb < 8; kb++) {
            mx0 = fmaxf(mx0, fmaxf(acc[kb][0], acc[kb][1]));
            mx1 = fmaxf(mx1, fmaxf(acc[kb][2], acc[kb][3]));
        }
        mx0 = fmaxf(mx0, __shfl_xor_sync(0xffffffffu, mx0, 1));
        mx0 = fmaxf(mx0, __shfl_xor_sync(0xffffffffu, mx0, 2));
        mx1 = fmaxf(mx1, __shfl_xor_sync(0xffffffffu, mx1, 1));
        mx1 = fmaxf(mx1, __shfl_xor_sync(0xffffffffu, mx1, 2));

        float sum0 = 0.f, sum1 = 0.f;
        #pragma unroll
        for (int kb = 0; kb < 8; kb++) {
            acc[kb][0] = __expf(acc[kb][0] - mx0);
            acc[kb][1] = __expf(acc[kb][1] - mx0);
            acc[kb][2] = __expf(acc[kb][2] - mx1);
            acc[kb][3] = __expf(acc[kb][3] - mx1);
            sum0 += acc[kb][0] + acc[kb][1];
            sum1 += acc[kb][2] + acc[kb][3];
        }
        sum0 += __shfl_xor_sync(0xffffffffu, sum0, 1);
        sum0 += __shfl_xor_sync(0xffffffffu, sum0, 2);
        sum1 += __shfl_xor_sync(0xffffffffu, sum1, 1);
        sum1 += __shfl_xor_sync(0xffffffffu, sum1, 2);
        float inv0 = 1.f / sum0, inv1 = 1.f / sum1;

        // ---- pack P into bf16x3 A-fragments ----
        unsigned pah[4][4], pal[4][4];
        #pragma unroll
        for (int kt = 0; kt < 4; kt++) {
            #pragma unroll
            for (int half = 0; half < 2; half++) {
                int kb = 2 * kt + half;
                float p0 = acc[kb][0] * inv0, p1 = acc[kb][1] * inv0;
                float p2 = acc[kb][2] * inv1, p3 = acc[kb][3] * inv1;
                __nv_bfloat16 h0, l0, h1, l1, h2, l2, h3, l3;
                split2(p0, h0, l0); split2(p1, h1, l1);
                split2(p2, h2, l2); split2(p3, h3, l3);
                pah[kt][half * 2]     = pack_bf16(h0, h1);
                pah[kt][half * 2 + 1] = pack_bf16(h2, h3);
                pal[kt][half * 2]     = pack_bf16(l0, l1);
                pal[kt][half * 2 + 1] = pack_bf16(l2, l3);
            }
        }

        // ---- values ----
        float acc2[8][4];
        #pragma unroll
        for (int mb = 0; mb < 8; mb++)
            #pragma unroll
            for (int i = 0; i < 4; i++) acc2[mb][i] = 0.f;

        #pragma unroll
        for (int kt = 0; kt < 4; kt++) {
            #pragma unroll
            for (int p = 0; p < 4; p++) {
                unsigned bh[4], bl[4];
                ldsm_x4(bh, &vph[(p * 16 + brow) * 72 + kt * 16 + bcol8]);
                ldsm_x4(bl, &vpl[(p * 16 + brow) * 72 + kt * 16 + bcol8]);
                mma16816(acc2[2 * p],     pah[kt], bh);
                mma16816(acc2[2 * p],     pah[kt], bl);
                mma16816(acc2[2 * p],     pal[kt], bh);
                mma16816(acc2[2 * p + 1], pah[kt], bh + 2);
                mma16816(acc2[2 * p + 1], pah[kt], bl + 2);
                mma16816(acc2[2 * p + 1], pal[kt], bh + 2);
            }
        }

        // stage output in smem (stride OSTR; even -> aligned float2 stores)
        #pragma unroll
        for (int mb = 0; mb < 8; mb++) {
            int ob = (r0 + gid) * OSTR + mb * 8 + 2 * tid;
            *(float2*)&outb[ob]             = make_float2(acc2[mb][0], acc2[mb][1]);
            *(float2*)&outb[ob + 8 * OSTR]  = make_float2(acc2[mb][2], acc2[mb][3]);
        }
        __syncthreads();

        // permuted writeback: x[b, m*(H*N) + h*N + n]; quad-contiguous 64B writes
        {
            int m = t >> 2;
            float* od = x + (size_t)b * (NN * NC) + (size_t)m * (NH * NN)
                          + (size_t)h * NN + nt * 512 + tile * 128;
            #pragma unroll
            for (int j = 0; j < 8; j++) {
                int r = (t & 3) * 4 + j * 16;
                float4 o;
                o.x = outb[(r + 0) * OSTR + m];
                o.y = outb[(r + 1) * OSTR + m];
                o.z = outb[(r + 2) * OSTR + m];
                o.w = outb[(r + 3) * OSTR + m];
                *(float4*)&od[r] = o;
            }
        }
        __syncthreads();   // protect outb reuse by next tile
    }
}

// ---------------------------------------------------------------------------
extern "C" void kernel_launch(void* const* d_in, const int* in_sizes, int n_in,
                              void* d_out, int out_size) {
    const float* skip = (const float*)d_in[0];
    const float* outq = (const float*)d_in[1];
    const float* gf   = (const float*)d_in[2];
    const float* ef1  = (const float*)d_in[3];
    const float* ef2  = (const float*)d_in[4];
    const float* temp = (const float*)d_in[5];
    float* x = (float*)d_out;

    const int ATTN_SMEM = 4 * 64 * 72 * 2 + 128 * OSTR * 4;   // 36864 + 37888 = 74752
    const int SKP_SMEM  = 4 * 2 * 32 * 72 * 2;                // 36864

    cudaFuncSetAttribute(k_attn, cudaFuncAttributeMaxDynamicSharedMemorySize, ATTN_SMEM);
    cudaFuncSetAttribute(k_skp,  cudaFuncAttributeMaxDynamicSharedMemorySize, SKP_SMEM);

    k_prep_ef2<<<(NN * NK) / 256, 256>>>(ef2);
    k_gvp<<<NB * NH, 256>>>(gf, ef1);
    k_skp<<<dim3(NCHUNK, 4, NB), 256, SKP_SMEM>>>(skip);
    k_reduce<<<(NB * NC * NK) / 256, 256>>>();
    k_attn<<<dim3(NN / 512, NH, NB), 256, ATTN_SMEM>>>(outq, temp, x);
}

// round 10
// speedup vs baseline: 1.9710x; 1.0496x over previous
#include <cuda_runtime.h>
#include <cuda_bf16.h>
#include <mma.h>
#include <math.h>

using namespace nvcuda;

#define NB 16
#define NN 8192
#define NC 256
#define NH 4
#define NK 64
#define NCHUNK 8

// Scratch (__device__ globals; no allocations allowed)
static __device__ float g_part[NCHUNK * NB * NC * NK];          // partials
static __device__ __nv_bfloat16 g_ef2h[NN * NK], g_ef2l[NN * NK];           // [n][k]
static __device__ __nv_bfloat16 g_skph[NB * NC * NK], g_skpl[NB * NC * NK]; // [b][h][k][d]
static __device__ __nv_bfloat16 g_vph[NB * NH * 64 * 64], g_vpl[NB * NH * 64 * 64]; // [b][h][m][k]

__device__ __forceinline__ void split2(float v, __nv_bfloat16& hi, __nv_bfloat16& lo) {
    hi = __float2bfloat16_rn(v);
    lo = __float2bfloat16_rn(v - __bfloat162float(hi));
}

// mma.sync m16n8k16 row.col bf16 -> f32, D += A*B
__device__ __forceinline__ void mma16816(float* c, const unsigned* a, const unsigned* b) {
    asm volatile(
        "mma.sync.aligned.m16n8k16.row.col.f32.bf16.bf16.f32 "
        "{%0,%1,%2,%3}, {%4,%5,%6,%7}, {%8,%9}, {%0,%1,%2,%3};"
        : "+f"(c[0]), "+f"(c[1]), "+f"(c[2]), "+f"(c[3])
        : "r"(a[0]), "r"(a[1]), "r"(a[2]), "r"(a[3]), "r"(b[0]), "r"(b[1]));
}

__device__ __forceinline__ void ldsm_x4(unsigned* r, const void* p) {
    unsigned a = (unsigned)__cvta_generic_to_shared(p);
    asm volatile("ldmatrix.sync.aligned.m8n8.x4.shared.b16 {%0,%1,%2,%3}, [%4];"
        : "=r"(r[0]), "=r"(r[1]), "=r"(r[2]), "=r"(r[3]) : "r"(a));
}

__device__ __forceinline__ unsigned pack_bf16(__nv_bfloat16 lo, __nv_bfloat16 hi) {
    __nv_bfloat162 p = __halves2bfloat162(lo, hi);   // .x = low half
    return *(unsigned*)&p;
}

__device__ __forceinline__ void cp_async16(void* smem, const void* gmem) {
    unsigned s = (unsigned)__cvta_generic_to_shared(smem);
    asm volatile("cp.async.cg.shared.global [%0], [%1], 16;" :: "r"(s), "l"(gmem));
}
__device__ __forceinline__ void cp_commit() { asm volatile("cp.async.commit_group;"); }
__device__ __forceinline__ void cp_wait0()  { asm volatile("cp.async.wait_group 0;" ::: "memory"); }

// ---------------------------------------------------------------------------
__global__ void k_prep_ef2(const float* __restrict__ ef2) {
    int i = blockIdx.x * 256 + threadIdx.x;
    split2(ef2[i], g_ef2h[i], g_ef2l[i]);
}

// global_vp (fp32, tiny), fused split + transpose epilogue:
// g_vph[bh][m][k=d1] = split(sum_n1 gf[b,n1,h*64+d1]*EF1[n1,m])
__global__ void k_gvp(const float* __restrict__ gf, const float* __restrict__ ef1) {
    int bh = blockIdx.x, b = bh >> 2, h = bh & 3;
    __shared__ float gs[64][64];
    __shared__ float es[64][64];
    int t = threadIdx.x;
    for (int i = t; i < 4096; i += 256) {
        int r = i >> 6, c = i & 63;
        gs[r][c] = gf[(b * 64 + r) * 256 + h * 64 + c];
        es[r][c] = ef1[i];
    }
    __syncthreads();
    int d0 = (t >> 4) << 2, m0 = (t & 15) << 2;
    float acc[4][4] = {};
    for (int n1 = 0; n1 < 64; n1++) {
        float4 a = *(const float4*)&gs[n1][d0];
        float4 v = *(const float4*)&es[n1][m0];
        float av[4] = {a.x, a.y, a.z, a.w};
        float bv[4] = {v.x, v.y, v.z, v.w};
        #pragma unroll
        for (int i = 0; i < 4; i++)
            #pragma unroll
            for (int j = 0; j < 4; j++)
                acc[i][j] += av[i] * bv[j];
    }
    size_t base = (size_t)bh * 4096;
    #pragma unroll
    for (int i = 0; i < 4; i++)
        #pragma unroll
        for (int j = 0; j < 4; j++) {
            __nv_bfloat16 hi, lo;
            split2(acc[i][j], hi, lo);
            size_t o = base + (size_t)(m0 + j) * 64 + (d0 + i);  // [m][k]
            g_vph[o] = hi;
            g_vpl[o] = lo;
        }
}

// ---------------------------------------------------------------------------
// skip_kp partials (wmma bf16x3).
// 32-row supersteps, 2-stage ping-pong (36.9 KB smem -> occupancy 4,
// all 512 CTAs resident in ONE wave). One barrier per superstep.
// part[chunk][b][c][k] = sum_{n in chunk} skip[b,n,c]*EF2[n,k]
// ---------------------------------------------------------------------------
__global__ void __launch_bounds__(256) k_skp(const float* __restrict__ skip) {
    extern __shared__ char sm[];
    __nv_bfloat16* ash = (__nv_bfloat16*)sm;            // [2][32][72]
    __nv_bfloat16* asl = ash + 2 * 32 * 72;
    __nv_bfloat16* bsh = asl + 2 * 32 * 72;
    __nv_bfloat16* bsl = bsh + 2 * 32 * 72;

    int chunk = blockIdx.x, ct = blockIdx.y, b = blockIdx.z;
    int t = threadIdx.x, w = t >> 5;

    wmma::fragment<wmma::accumulator, 16, 16, 16, float> acc[2];
    wmma::fill_fragment(acc[0], 0.f);
    wmma::fill_fragment(acc[1], 0.f);
    int c0 = (w >> 1) * 16;
    int kc = (w & 1) * 32;

    int lr = t >> 4, lc4 = (t & 15) * 4;                 // skip loader: rows lr, lr+16
    int er = (t & 127) >> 3, ek8 = (t & 7) * 8;          // ef2: rows er, er+16
    bool hiload = (t < 128);

    size_t sbase = ((size_t)b * NN + chunk * 1024) * NC + ct * 64 + lc4;
    size_t ebase = (size_t)(chunk * 1024 + er) * 64 + ek8;
    const __nv_bfloat16* esrc = hiload ? g_ef2h : g_ef2l;
    __nv_bfloat16* bdst = hiload ? bsh : bsl;

    float4 v[2];

    // prologue: superstep 0 into stage 0
    #pragma unroll
    for (int j = 0; j < 2; j++) {
        cp_async16(&bdst[(j * 16 + er) * 72 + ek8], &esrc[ebase + (size_t)(j * 16) * 64]);
        v[j] = *(const float4*)&skip[sbase + (size_t)(j * 16 + lr) * NC];
    }
    cp_commit();
    #pragma unroll
    for (int j = 0; j < 2; j++) {
        __nv_bfloat16 hx, lx, hy, ly, hz, lz, hw, lw;
        split2(v[j].x, hx, lx); split2(v[j].y, hy, ly);
        split2(v[j].z, hz, lz); split2(v[j].w, hw, lw);
        int row = j * 16 + lr;
        *(uint2*)&ash[row * 72 + lc4] = make_uint2(pack_bf16(hx, hy), pack_bf16(hz, hw));
        *(uint2*)&asl[row * 72 + lc4] = make_uint2(pack_bf16(lx, ly), pack_bf16(lz, lw));
    }
    cp_wait0();
    __syncthreads();

    for (int ss = 0; ss < 32; ss++) {
        int cur = ss & 1, nxt = cur ^ 1;

        // issue next superstep's loads early (overlap with the MMA block)
        if (ss < 31) {
            size_t srow = sbase + (size_t)((ss + 1) * 32) * NC;
            size_t eoff = ebase + (size_t)((ss + 1) * 32) * 64;
            #pragma unroll
            for (int j = 0; j < 2; j++) {
                cp_async16(&bdst[(nxt * 32 + j * 16 + er) * 72 + ek8],
                           &esrc[eoff + (size_t)(j * 16) * 64]);
                v[j] = *(const float4*)&skip[srow + (size_t)(j * 16 + lr) * NC];
            }
            cp_commit();
        }

        // MMA block: 2 sub-steps of 16 rows
        #pragma unroll
        for (int sub = 0; sub < 2; sub++) {
            wmma::fragment<wmma::matrix_a, 16, 16, 16, __nv_bfloat16, wmma::col_major> ah, al;
            wmma::load_matrix_sync(ah, &ash[(cur * 32 + sub * 16) * 72 + c0], 72);
            wmma::load_matrix_sync(al, &asl[(cur * 32 + sub * 16) * 72 + c0], 72);
            #pragma unroll
            for (int kt = 0; kt < 2; kt++) {
                wmma::fragment<wmma::matrix_b, 16, 16, 16, __nv_bfloat16, wmma::row_major> bh, bl;
                wmma::load_matrix_sync(bh, &bsh[(cur * 32 + sub * 16) * 72 + kc + kt * 16], 72);
                wmma::load_matrix_sync(bl, &bsl[(cur * 32 + sub * 16) * 72 + kc + kt * 16], 72);
                wmma::mma_sync(acc[kt], ah, bh, acc[kt]);
                wmma::mma_sync(acc[kt], ah, bl, acc[kt]);
                wmma::mma_sync(acc[kt], al, bh, acc[kt]);
            }
        }

        if (ss < 31) {
            #pragma unroll
            for (int j = 0; j < 2; j++) {
                __nv_bfloat16 hx, lx, hy, ly, hz, lz, hw, lw;
                split2(v[j].x, hx, lx); split2(v[j].y, hy, ly);
                split2(v[j].z, hz, lz); split2(v[j].w, hw, lw);
                int row = nxt * 32 + j * 16 + lr;
                *(uint2*)&ash[row * 72 + lc4] = make_uint2(pack_bf16(hx, hy), pack_bf16(hz, hw));
                *(uint2*)&asl[row * 72 + lc4] = make_uint2(pack_bf16(lx, ly), pack_bf16(lz, lw));
            }
        }
        cp_wait0();
        __syncthreads();
    }

    float* p = g_part + (((size_t)chunk * NB + b) * NC + ct * 64 + c0) * 64 + kc;
    wmma::store_matrix_sync(p, acc[0], 64, wmma::mem_row_major);
    wmma::store_matrix_sync(p + 16, acc[1], 64, wmma::mem_row_major);
}

// ---------------------------------------------------------------------------
// Reduce partials (fixed order), split + TRANSPOSE into g_skp[b][h][k][d]
// ---------------------------------------------------------------------------
__global__ void k_reduce() {
    int i = blockIdx.x * 256 + threadIdx.x;      // over NB*NC*NK = 262144
    float s = 0.f;
    #pragma unroll
    for (int c = 0; c < NCHUNK; c++) s += g_part[(size_t)c * (NB * NC * NK) + i];
    int b = i >> 14, rem = i & 16383, c = rem >> 6, k = rem & 63;
    int h = c >> 6, d = c & 63;
    size_t o = (((size_t)(b * NH + h) * 64 + k) * 64) + d;
    split2(s, g_skph[o], g_skpl[o]);
}

// ---------------------------------------------------------------------------
// Fused attention: q A-fragments direct from global, B via ldmatrix,
// register softmax + P-in-registers, DIRECT fragment->global writeback
// (each store instr = 4 full 32B sectors; no smem staging, no per-tile
// barriers). 2 row-tiles (256 rows) per block; grid 2048 for wave balance.
// ---------------------------------------------------------------------------
#define TILES 2

__global__ void __launch_bounds__(256) k_attn(
    const float* __restrict__ outq, const float* __restrict__ temp,
    float* __restrict__ x)
{
    extern __shared__ char smbuf[];
    __nv_bfloat16* sph = (__nv_bfloat16*)smbuf;          // 64x72  skpT [k][d]
    __nv_bfloat16* spl = sph + 64 * 72;
    __nv_bfloat16* vph = spl + 64 * 72;                  // 64x72  vpT  [m][k]
    __nv_bfloat16* vpl = vph + 64 * 72;

    int nt = blockIdx.x, h = blockIdx.y, b = blockIdx.z;
    int t = threadIdx.x, w = t >> 5, lane = t & 31;
    int gid = lane >> 2, tid = lane & 3;
    int r0 = w * 16;

    int brow = (lane & 7) + ((lane >> 4) << 3);
    int bcol8 = ((lane >> 3) & 1) * 8;

    {
        size_t base = (size_t)(b * NH + h) * 4096;
        for (int i = t; i < 512; i += 256) {
            int r = i >> 3, k8 = (i & 7) * 8;
            *(uint4*)&sph[r * 72 + k8] = *(const uint4*)&g_skph[base + r * 64 + k8];
            *(uint4*)&spl[r * 72 + k8] = *(const uint4*)&g_skpl[base + r * 64 + k8];
            *(uint4*)&vph[r * 72 + k8] = *(const uint4*)&g_vph[base + r * 64 + k8];
            *(uint4*)&vpl[r * 72 + k8] = *(const uint4*)&g_vpl[base + r * 64 + k8];
        }
    }
    float tempv = temp[h];
    __syncthreads();

    #pragma unroll 1
    for (int tile = 0; tile < TILES; tile++) {
        int rowbase = nt * (TILES * 128) + tile * 128 + r0 + gid;
        const float* qr0 = outq + ((size_t)b * NN + rowbase) * NC + h * 64;
        const float* qr8 = qr0 + 8 * NC;

        // ---- logits ----
        float acc[8][4];
        #pragma unroll
        for (int kb = 0; kb < 8; kb++)
            #pragma unroll
            for (int i = 0; i < 4; i++) acc[kb][i] = 0.f;

        #pragma unroll
        for (int dt = 0; dt < 4; dt++) {
            float2 v00 = *(const float2*)&qr0[dt * 16 + 2 * tid];
            float2 v10 = *(const float2*)&qr8[dt * 16 + 2 * tid];
            float2 v01 = *(const float2*)&qr0[dt * 16 + 2 * tid + 8];
            float2 v11 = *(const float2*)&qr8[dt * 16 + 2 * tid + 8];
            unsigned ah[4], al[4];
            {
                __nv_bfloat16 ha, la, hb, lb;
                split2(v00.x, ha, la); split2(v00.y, hb, lb);
                ah[0] = pack_bf16(ha, hb); al[0] = pack_bf16(la, lb);
                split2(v10.x, ha, la); split2(v10.y, hb, lb);
                ah[1] = pack_bf16(ha, hb); al[1] = pack_bf16(la, lb);
                split2(v01.x, ha, la); split2(v01.y, hb, lb);
                ah[2] = pack_bf16(ha, hb); al[2] = pack_bf16(la, lb);
                split2(v11.x, ha, la); split2(v11.y, hb, lb);
                ah[3] = pack_bf16(ha, hb); al[3] = pack_bf16(la, lb);
            }
            #pragma unroll
            for (int p = 0; p < 4; p++) {
                unsigned bh[4], bl[4];
                ldsm_x4(bh, &sph[(p * 16 + brow) * 72 + dt * 16 + bcol8]);
                ldsm_x4(bl, &spl[(p * 16 + brow) * 72 + dt * 16 + bcol8]);
                mma16816(acc[2 * p],     ah, bh);
                mma16816(acc[2 * p],     ah, bl);
                mma16816(acc[2 * p],     al, bh);
                mma16816(acc[2 * p + 1], ah, bh + 2);
                mma16816(acc[2 * p + 1], ah, bl + 2);
                mma16816(acc[2 * p + 1], al, bh + 2);
            }
        }

        // ---- softmax in registers ----
        #pragma unroll
        for (int kb = 0; kb < 8; kb++)
            #pragma unroll
            for (int i = 0; i < 4; i++) acc[kb][i] *= tempv;

        float mx0 = -1e30f, mx1 = -1e30f;
        #pragma unroll
        for (int kb = 0; kb < 8; kb++) {
            mx0 = fmaxf(mx0, fmaxf(acc[kb][0], acc[kb][1]));
            mx1 = fmaxf(mx1, fmaxf(acc[kb][2], acc[kb][3]));
        }
        mx0 = fmaxf(mx0, __shfl_xor_sync(0xffffffffu, mx0, 1));
        mx0 = fmaxf(mx0, __shfl_xor_sync(0xffffffffu, mx0, 2));
        mx1 = fmaxf(mx1, __shfl_xor_sync(0xffffffffu, mx1, 1));
        mx1 = fmaxf(mx1, __shfl_xor_sync(0xffffffffu, mx1, 2));

        float sum0 = 0.f, sum1 = 0.f;
        #pragma unroll
        for (int kb = 0; kb < 8; kb++) {
            acc[kb][0] = __expf(acc[kb][0] - mx0);
            acc[kb][1] = __expf(acc[kb][1] - mx0);
            acc[kb][2] = __expf(acc[kb][2] - mx1);
            acc[kb][3] = __expf(acc[kb][3] - mx1);
            sum0 += acc[kb][0] + acc[kb][1];
            sum1 += acc[kb][2] + acc[kb][3];
        }
        sum0 += __shfl_xor_sync(0xffffffffu, sum0, 1);
        sum0 += __shfl_xor_sync(0xffffffffu, sum0, 2);
        sum1 += __shfl_xor_sync(0xffffffffu, sum1, 1);
        sum1 += __shfl_xor_sync(0xffffffffu, sum1, 2);
        float inv0 = 1.f / sum0, inv1 = 1.f / sum1;

        // ---- pack P into bf16x3 A-fragments ----
        unsigned pah[4][4], pal[4][4];
        #pragma unroll
        for (int kt = 0; kt < 4; kt++) {
            #pragma unroll
            for (int half = 0; half < 2; half++) {
                int kb = 2 * kt + half;
                float p0 = acc[kb][0] * inv0, p1 = acc[kb][1] * inv0;
                float p2 = acc[kb][2] * inv1, p3 = acc[kb][3] * inv1;
                __nv_bfloat16 h0, l0, h1, l1, h2, l2, h3, l3;
                split2(p0, h0, l0); split2(p1, h1, l1);
                split2(p2, h2, l2); split2(p3, h3, l3);
                pah[kt][half * 2]     = pack_bf16(h0, h1);
                pah[kt][half * 2 + 1] = pack_bf16(h2, h3);
                pal[kt][half * 2]     = pack_bf16(l0, l1);
                pal[kt][half * 2 + 1] = pack_bf16(l2, l3);
            }
        }

        // ---- values ----
        float acc2[8][4];
        #pragma unroll
        for (int mb = 0; mb < 8; mb++)
            #pragma unroll
            for (int i = 0; i < 4; i++) acc2[mb][i] = 0.f;

        #pragma unroll
        for (int kt = 0; kt < 4; kt++) {
            #pragma unroll
            for (int p = 0; p < 4; p++) {
                unsigned bh[4], bl[4];
                ldsm_x4(bh, &vph[(p * 16 + brow) * 72 + kt * 16 + bcol8]);
                ldsm_x4(bl, &vpl[(p * 16 + brow) * 72 + kt * 16 + bcol8]);
                mma16816(acc2[2 * p],     pah[kt], bh);
                mma16816(acc2[2 * p],     pah[kt], bl);
                mma16816(acc2[2 * p],     pal[kt], bh);
                mma16816(acc2[2 * p + 1], pah[kt], bh + 2);
                mma16816(acc2[2 * p + 1], pah[kt], bl + 2);
                mma16816(acc2[2 * p + 1], pal[kt], bh + 2);
            }
        }

        // ---- direct writeback: x[b, m*(H*N) + h*N + n] ----
        // Fragment (mb,i) -> m = mb*8 + 2*tid + (i&1), n = rowbase + (i>>1)*8.
        // Per warp-store: 4 m-columns x 8 consecutive n = 4 full 32B sectors.
        {
            const size_t MS = (size_t)NH * NN;  // m stride
            float* od = x + (size_t)b * (NN * NC) + (size_t)h * NN + rowbase;
            #pragma unroll
            for (int mb = 0; mb < 8; mb++) {
                size_t m0 = (size_t)(mb * 8 + 2 * tid);
                od[m0 * MS]           = acc2[mb][0];
                od[(m0 + 1) * MS]     = acc2[mb][1];
                od[m0 * MS + 8]       = acc2[mb][2];
                od[(m0 + 1) * MS + 8] = acc2[mb][3];
            }
        }
    }
}

// ---------------------------------------------------------------------------
extern "C" void kernel_launch(void* const* d_in, const int* in_sizes, int n_in,
                              void* d_out, int out_size) {
    const float* skip = (const float*)d_in[0];
    const float* outq = (const float*)d_in[1];
    const float* gf   = (const float*)d_in[2];
    const float* ef1  = (const float*)d_in[3];
    const float* ef2  = (const float*)d_in[4];
    const float* temp = (const float*)d_in[5];
    float* x = (float*)d_out;

    const int ATTN_SMEM = 4 * 64 * 72 * 2;                    // 36864
    const int SKP_SMEM  = 4 * 2 * 32 * 72 * 2;                // 36864

    cudaFuncSetAttribute(k_attn, cudaFuncAttributeMaxDynamicSharedMemorySize, ATTN_SMEM);
    cudaFuncSetAttribute(k_skp,  cudaFuncAttributeMaxDynamicSharedMemorySize, SKP_SMEM);

    k_prep_ef2<<<(NN * NK) / 256, 256>>>(ef2);
    k_gvp<<<NB * NH, 256>>>(gf, ef1);
    k_skp<<<dim3(NCHUNK, 4, NB), 256, SKP_SMEM>>>(skip);
    k_reduce<<<(NB * NC * NK) / 256, 256>>>();
    k_attn<<<dim3(NN / (TILES * 128), NH, NB), 256, ATTN_SMEM>>>(outq, temp, x);
}